// round 1
// baseline (speedup 1.0000x reference)
#include <cuda_runtime.h>

#define C   128
#define LDD 130   // padded smem row stride (conflict-free column reads)
#define TM  128   // rows per CTA tile
#define NT  256   // threads per CTA

// Scratch (device globals: allocation-free rule)
static __device__ __align__(16) float g_xf[20480 * C];
static __device__ __align__(16) float g_agg[20480 * C];

__device__ __forceinline__ float ssp_f(float x) {
    // shifted softplus: log(0.5*e^x + 0.5) = max(x,0) + log1p(e^-|x|) - log2
    return fmaxf(x, 0.0f) + log1pf(__expf(-fabsf(x))) - 0.693147180559945f;
}

__device__ __forceinline__ void load_w(float* Ws, const float* __restrict__ W) {
    const float4* s = (const float4*)W;
    float4* d = (float4*)Ws;
    int tid = threadIdx.x;
#pragma unroll
    for (int i = 0; i < (C * C / 4) / NT; ++i)
        d[tid + i * NT] = s[tid + i * NT];
}

__device__ __forceinline__ void load_d(float* Ds, const float* __restrict__ src,
                                       int base_row, int nrow) {
    int tid = threadIdx.x;
#pragma unroll
    for (int it = 0; it < (TM * (C / 4)) / NT; ++it) {
        int idx = tid + it * NT;
        int r = idx >> 5;        // / (C/4)
        int c4 = idx & 31;
        float4 v = make_float4(0.f, 0.f, 0.f, 0.f);
        int gr = base_row + r;
        if (gr < nrow) v = ((const float4*)src)[gr * (C / 4) + c4];
        float* p = Ds + r * LDD + c4 * 4;
        p[0] = v.x; p[1] = v.y; p[2] = v.z; p[3] = v.w;
    }
}

// acc[i][j] is a packed f32x2 holding output cols {ct*2 + j*32, +1} of row rt*8+i.
// Column interleave (pairs strided by 32) keeps smem B-row reads conflict-free.
__device__ __forceinline__ void gemm_128(const float* Ds, const float* Ws,
                                         int rt, int ct,
                                         unsigned long long acc[8][4]) {
    const float* dp = Ds + rt * 8 * LDD;
    const float* wp = Ws + ct * 2;
#pragma unroll
    for (int i = 0; i < 8; ++i)
#pragma unroll
        for (int j = 0; j < 4; ++j) acc[i][j] = 0ULL;
#pragma unroll 8
    for (int k = 0; k < C; ++k) {
        unsigned long long b[4];
#pragma unroll
        for (int j = 0; j < 4; ++j)
            b[j] = *(const unsigned long long*)(wp + k * C + j * 32);
#pragma unroll
        for (int i = 0; i < 8; ++i) {
            unsigned int au = __float_as_uint(dp[i * LDD + k]);
            unsigned long long a2;
            asm("mov.b64 %0, {%1, %1};" : "=l"(a2) : "r"(au));
#pragma unroll
            for (int j = 0; j < 4; ++j)
                asm("fma.rn.f32x2 %0, %1, %2, %3;"
                    : "=l"(acc[i][j])
                    : "l"(a2), "l"(b[j]), "l"(acc[i][j]));
        }
    }
}

__device__ __forceinline__ float2 unpack2(unsigned long long v) {
    unsigned int lo, hi;
    asm("mov.b64 {%0, %1}, %2;" : "=r"(lo), "=r"(hi) : "l"(v));
    return make_float2(__uint_as_float(lo), __uint_as_float(hi));
}

// ---------------- Kernel 1: xf = x @ Wi  (+ zero agg tiles) ----------------
extern "C" __global__ void __launch_bounds__(NT, 1)
k_xf(const float* __restrict__ x, const float* __restrict__ Wi, int na) {
    extern __shared__ float smem[];
    float* Ws = smem;
    float* Ds = smem + C * C;
    int tid = threadIdx.x, rt = tid >> 4, ct = tid & 15;
    int base = blockIdx.x * TM;

    // zero agg for this atom tile
#pragma unroll
    for (int it = 0; it < (TM * (C / 4)) / NT; ++it) {
        int idx = tid + it * NT;
        int r = idx >> 5, c4 = idx & 31;
        int gr = base + r;
        if (gr < na) ((float4*)(g_agg + (size_t)gr * C))[c4] = make_float4(0.f, 0.f, 0.f, 0.f);
    }

    load_w(Ws, Wi);
    load_d(Ds, x, base, na);
    __syncthreads();

    unsigned long long acc[8][4];
    gemm_128(Ds, Ws, rt, ct, acc);

#pragma unroll
    for (int i = 0; i < 8; ++i) {
        int r = base + rt * 8 + i;
        if (r < na) {
#pragma unroll
            for (int j = 0; j < 4; ++j) {
                float2 v = unpack2(acc[i][j]);
                *(float2*)(&g_xf[r * C + ct * 2 + j * 32]) = v;
            }
        }
    }
}

// ---- Kernel 2: fused edge pipeline: 2 GEMMs + ssp + gather + segmented scatter ----
extern "C" __global__ void __launch_bounds__(NT, 1)
k_edges(const float* __restrict__ dijk,
        const int* __restrict__ idx_j,
        const int* __restrict__ seg_i,
        const int* __restrict__ seg_j,
        const float* __restrict__ W1, const float* __restrict__ b1,
        const float* __restrict__ W2, const float* __restrict__ b2,
        int ne) {
    extern __shared__ float smem[];
    float* Ws = smem;
    float* Ds = smem + C * C;
    float* Hs = Ds + TM * LDD;
    int* s_aj = (int*)(Hs + TM * LDD);
    int* s_ti = s_aj + TM;

    int tid = threadIdx.x, rt = tid >> 4, ct = tid & 15;
    int base = blockIdx.x * TM;

    float b1v[8], b2v[8];
#pragma unroll
    for (int j = 0; j < 4; ++j) {
        int c0 = ct * 2 + j * 32;
        b1v[2 * j] = b1[c0]; b1v[2 * j + 1] = b1[c0 + 1];
        b2v[2 * j] = b2[c0]; b2v[2 * j + 1] = b2[c0 + 1];
    }

    load_w(Ws, W1);
    load_d(Ds, dijk, base, ne);
    __syncthreads();

    unsigned long long acc[8][4];
    gemm_128(Ds, Ws, rt, ct, acc);

    // h1 = ssp(D@W1 + b1) -> Hs
#pragma unroll
    for (int i = 0; i < 8; ++i) {
#pragma unroll
        for (int j = 0; j < 4; ++j) {
            float2 v = unpack2(acc[i][j]);
            v.x = ssp_f(v.x + b1v[2 * j]);
            v.y = ssp_f(v.y + b1v[2 * j + 1]);
            *(float2*)(&Hs[(rt * 8 + i) * LDD + ct * 2 + j * 32]) = v;
        }
    }
    __syncthreads();

    load_w(Ws, W2);
    if (tid < TM) {
        int e = base + tid;
        int aj = 0, ti = -1;
        if (e < ne) {
            int p = seg_j[e];
            aj = idx_j[p];
            ti = seg_i[p];
        }
        s_aj[tid] = aj;
        s_ti[tid] = ti;
    }
    __syncthreads();

    gemm_128(Hs, Ws, rt, ct, acc);

    // epilogue: w = ssp(h1@W2 + b2); msg = xf[aj] * w; run-length reduce by
    // sorted target atom; atomicAdd flush per run.
    int cur_t = -1;
    float2 racc[4] = {{0.f, 0.f}, {0.f, 0.f}, {0.f, 0.f}, {0.f, 0.f}};
#pragma unroll
    for (int i = 0; i < 8; ++i) {
        int el = rt * 8 + i;
        int t = s_ti[el];
        if (t != cur_t) {
            if (cur_t >= 0) {
#pragma unroll
                for (int j = 0; j < 4; ++j) {
                    float* a = &g_agg[(size_t)cur_t * C + ct * 2 + j * 32];
                    atomicAdd(a, racc[j].x);
                    atomicAdd(a + 1, racc[j].y);
                    racc[j] = make_float2(0.f, 0.f);
                }
            }
            cur_t = t;
        }
        if (t < 0) continue;
        const float2* xrow = (const float2*)(g_xf + (size_t)s_aj[el] * C);
#pragma unroll
        for (int j = 0; j < 4; ++j) {
            float2 w = unpack2(acc[i][j]);
            w.x = ssp_f(w.x + b2v[2 * j]);
            w.y = ssp_f(w.y + b2v[2 * j + 1]);
            float2 xv = xrow[ct + 16 * j];
            racc[j].x += w.x * xv.x;
            racc[j].y += w.y * xv.y;
        }
    }
    if (cur_t >= 0) {
#pragma unroll
        for (int j = 0; j < 4; ++j) {
            float* a = &g_agg[(size_t)cur_t * C + ct * 2 + j * 32];
            atomicAdd(a, racc[j].x);
            atomicAdd(a + 1, racc[j].y);
        }
    }
}

// ------- Kernel 3: h = ssp(agg@Wo+bo); v = h@Wd+bd; y = x+v; write (y, v) -------
extern "C" __global__ void __launch_bounds__(NT, 1)
k_out(const float* __restrict__ x,
      const float* __restrict__ Wo, const float* __restrict__ bo,
      const float* __restrict__ Wd, const float* __restrict__ bd,
      float* __restrict__ out_y, float* __restrict__ out_v, int na) {
    extern __shared__ float smem[];
    float* Ws = smem;
    float* Ds = smem + C * C;
    float* Hs = Ds + TM * LDD;
    int tid = threadIdx.x, rt = tid >> 4, ct = tid & 15;
    int base = blockIdx.x * TM;

    float bov[8], bdv[8];
#pragma unroll
    for (int j = 0; j < 4; ++j) {
        int c0 = ct * 2 + j * 32;
        bov[2 * j] = bo[c0]; bov[2 * j + 1] = bo[c0 + 1];
        bdv[2 * j] = bd[c0]; bdv[2 * j + 1] = bd[c0 + 1];
    }

    load_w(Ws, Wo);
    load_d(Ds, g_agg, base, na);
    __syncthreads();

    unsigned long long acc[8][4];
    gemm_128(Ds, Ws, rt, ct, acc);

#pragma unroll
    for (int i = 0; i < 8; ++i) {
#pragma unroll
        for (int j = 0; j < 4; ++j) {
            float2 v = unpack2(acc[i][j]);
            v.x = ssp_f(v.x + bov[2 * j]);
            v.y = ssp_f(v.y + bov[2 * j + 1]);
            *(float2*)(&Hs[(rt * 8 + i) * LDD + ct * 2 + j * 32]) = v;
        }
    }
    __syncthreads();

    load_w(Ws, Wd);
    __syncthreads();

    gemm_128(Hs, Ws, rt, ct, acc);

#pragma unroll
    for (int i = 0; i < 8; ++i) {
        int r = base + rt * 8 + i;
        if (r < na) {
#pragma unroll
            for (int j = 0; j < 4; ++j) {
                int c0 = ct * 2 + j * 32;
                float2 v = unpack2(acc[i][j]);
                v.x += bdv[2 * j];
                v.y += bdv[2 * j + 1];
                float2 xv = *(const float2*)(&x[(size_t)r * C + c0]);
                float2 y = make_float2(xv.x + v.x, xv.y + v.y);
                *(float2*)(&out_v[(size_t)r * C + c0]) = v;
                *(float2*)(&out_y[(size_t)r * C + c0]) = y;
            }
        }
    }
}

extern "C" void kernel_launch(void* const* d_in, const int* in_sizes, int n_in,
                              void* d_out, int out_size) {
    const float* x    = (const float*)d_in[0];
    const float* dijk = (const float*)d_in[1];
    const int*   idxj = (const int*)d_in[2];
    const int*   segi = (const int*)d_in[3];
    const int*   segj = (const int*)d_in[4];
    const float* W1   = (const float*)d_in[5];
    const float* b1   = (const float*)d_in[6];
    const float* W2   = (const float*)d_in[7];
    const float* b2   = (const float*)d_in[8];
    const float* Wi   = (const float*)d_in[9];
    const float* Wo   = (const float*)d_in[10];
    const float* bo   = (const float*)d_in[11];
    const float* Wd   = (const float*)d_in[12];
    const float* bd   = (const float*)d_in[13];

    int na = in_sizes[0] / C;
    int ne = in_sizes[2];

    float* out_y = (float*)d_out;
    float* out_v = out_y + (size_t)na * C;

    const int SMEM_XF  = (C * C + TM * LDD) * 4;                       // 132096
    const int SMEM_EDG = (C * C + 2 * TM * LDD) * 4 + 2 * TM * 4;      // 199680
    const int SMEM_OUT = (C * C + 2 * TM * LDD) * 4;                   // 198656

    cudaFuncSetAttribute(k_xf,    cudaFuncAttributeMaxDynamicSharedMemorySize, SMEM_XF);
    cudaFuncSetAttribute(k_edges, cudaFuncAttributeMaxDynamicSharedMemorySize, SMEM_EDG);
    cudaFuncSetAttribute(k_out,   cudaFuncAttributeMaxDynamicSharedMemorySize, SMEM_OUT);

    int g_atoms = (na + TM - 1) / TM;
    int g_edges = (ne + TM - 1) / TM;

    k_xf<<<g_atoms, NT, SMEM_XF>>>(x, Wi, na);
    k_edges<<<g_edges, NT, SMEM_EDG>>>(dijk, idxj, segi, segj, W1, b1, W2, b2, ne);
    k_out<<<g_atoms, NT, SMEM_OUT>>>(x, Wo, bo, Wd, bd, out_y, out_v, na);
}

// round 5
// speedup vs baseline: 1.5880x; 1.5880x over previous
#include <cuda_runtime.h>
#include <cstdint>

#define C   128
#define LDD 130   // FMA-path pad
#define LDK 132   // mma-path smem row stride (floats)
#define TM  128
#define NT  256

extern __shared__ char dynsmem[];

// ---------------- scratch (device globals; allocation-free rule) ----------------
static __device__ __align__(16) float g_xf[20480 * C];
static __device__ __align__(16) float g_agg[20480 * C];
static __device__ __align__(16) float g_W1t[C * C];
static __device__ __align__(16) float g_W2t[C * C];

__device__ __forceinline__ float ssp_f(float x) {
    float t = __expf(-fabsf(x));
    return fmaxf(x, 0.0f) + __logf(1.0f + t) - 0.693147180559945f;
}

__device__ __forceinline__ float to_tf32(float x) {
    uint32_t u;
    asm("cvt.rna.tf32.f32 %0, %1;" : "=r"(u) : "f"(x));
    return __uint_as_float(u);
}

__device__ __forceinline__ void mma_tf32(float* d, const uint32_t* a, const uint32_t* b) {
    asm volatile(
        "mma.sync.aligned.m16n8k8.row.col.f32.tf32.tf32.f32 "
        "{%0,%1,%2,%3}, {%4,%5,%6,%7}, {%8,%9}, {%0,%1,%2,%3};"
        : "+f"(d[0]), "+f"(d[1]), "+f"(d[2]), "+f"(d[3])
        : "r"(a[0]), "r"(a[1]), "r"(a[2]), "r"(a[3]), "r"(b[0]), "r"(b[1]));
}

// =====================================================================
// Edge kernel (mma.sync tf32): agg += scatter( ssp(ssp(dijk@W1+b1)@W2+b2) * xf[idx_j] )
// SMEM tile layout: row-major, LDK floats/row, k-columns interleaved inside
// each octet: logical k (within octet) j8 -> phys ((j8&3)<<1) | (j8>>2).
// This makes every mma fragment pair an 8-byte contiguous LDS.64.
// =====================================================================

// fill a 128x128 tile from a row-major [128,128] global src (tf32-rounded)
__device__ __forceinline__ void fill_w_tile(float* dst, const float* __restrict__ src, int tid) {
#pragma unroll
    for (int i = 0; i < 16; ++i) {
        int wg = (tid >> 5) + (i << 3);           // 0..127
        int row = (wg & 15) * 8 + ((tid >> 2) & 7);
        int c4  = (wg >> 4) * 4 + (tid & 3);
        float4 v = ((const float4*)src)[row * 32 + c4];
        float* d = dst + row * LDK + (c4 >> 1) * 8 + (c4 & 1);
        d[0] = to_tf32(v.x); d[2] = to_tf32(v.y); d[4] = to_tf32(v.z); d[6] = to_tf32(v.w);
    }
}

extern "C" __global__ void __launch_bounds__(NT, 1)
k_edges_mma(const float* __restrict__ dijk,
            const int* __restrict__ idx_j,
            const int* __restrict__ seg_i,
            const int* __restrict__ seg_j,
            const float* __restrict__ b1, const float* __restrict__ b2,
            int ne, int ntiles) {
    float* sA  = (float*)dynsmem;                 // 128 x LDK  (A tile / H tile / W tile)
    float* sB1 = sA + 128 * LDK;                  // W1t
    float* sB2 = sB1 + 128 * LDK;                 // W2t
    int* s_aj = (int*)(sB2 + 128 * LDK);
    int* s_ti = s_aj + TM;

    const int tid = threadIdx.x;
    const int wid = tid >> 5, lane = tid & 31;
    const int g = lane >> 2, c = lane & 3;
    const int mr = (wid & 1) * 64;                // warp row-block (64 rows)
    const int nc = (wid >> 1) * 32;               // warp col-block (32 cols)
    const int pe = ((c & 1) << 2) + (c >> 1);     // phys pos of logical col 2c within octet
    const int po = pe + 2;                        // phys pos of logical col 2c+1

    // per-thread bias registers for the 8 columns this thread owns (per n-tile)
    float be1[4], bo1[4], be2[4], bo2[4];
#pragma unroll
    for (int nt = 0; nt < 4; ++nt) {
        int col = nc + nt * 8 + 2 * c;
        be1[nt] = b1[col]; bo1[nt] = b1[col + 1];
        be2[nt] = b2[col]; bo2[nt] = b2[col + 1];
    }

    fill_w_tile(sB1, g_W1t, tid);
    fill_w_tile(sB2, g_W2t, tid);
    __syncthreads();

    for (int t = blockIdx.x; t < ntiles; t += gridDim.x) {
        const int base = t * TM;

        if (tid < TM) {
            int e = base + tid, aj = 0, ti = -1;
            if (e < ne) { int p = seg_j[e]; aj = idx_j[p]; ti = seg_i[p]; }
            s_aj[tid] = aj; s_ti[tid] = ti;
        }
        // ---- load + tf32-round A tile (dijk rows) ----
#pragma unroll
        for (int i = 0; i < 16; ++i) {
            int wg = (tid >> 5) + (i << 3);
            int row = (wg & 15) * 8 + ((tid >> 2) & 7);
            int c4  = (wg >> 4) * 4 + (tid & 3);
            float4 v = make_float4(0.f, 0.f, 0.f, 0.f);
            int gr = base + row;
            if (gr < ne) v = ((const float4*)dijk)[gr * 32 + c4];
            float* d = sA + row * LDK + (c4 >> 1) * 8 + (c4 & 1);
            d[0] = to_tf32(v.x); d[2] = to_tf32(v.y); d[4] = to_tf32(v.z); d[6] = to_tf32(v.w);
        }
        __syncthreads();

        // ================= GEMM1: D = A @ W1t^T =================
        float acc[4][4][4];
#pragma unroll
        for (int mt = 0; mt < 4; ++mt)
#pragma unroll
            for (int nt = 0; nt < 4; ++nt)
#pragma unroll
                for (int q = 0; q < 4; ++q) acc[mt][nt][q] = 0.f;
        {
            const float* pa = sA  + (mr + g) * LDK + 2 * c;
            const float* pb = sB1 + (nc + g) * LDK + 2 * c;
#pragma unroll
            for (int kk = 0; kk < 16; ++kk) {
                const int kb = kk * 8;
                uint32_t af[4][4], bf[4][2];
#pragma unroll
                for (int mt = 0; mt < 4; ++mt) {
                    float2 x = *(const float2*)(pa + mt * 16 * LDK + kb);
                    float2 y = *(const float2*)(pa + (mt * 16 + 8) * LDK + kb);
                    af[mt][0] = __float_as_uint(x.x); af[mt][2] = __float_as_uint(x.y);
                    af[mt][1] = __float_as_uint(y.x); af[mt][3] = __float_as_uint(y.y);
                }
#pragma unroll
                for (int nt = 0; nt < 4; ++nt) {
                    float2 z = *(const float2*)(pb + nt * 8 * LDK + kb);
                    bf[nt][0] = __float_as_uint(z.x); bf[nt][1] = __float_as_uint(z.y);
                }
#pragma unroll
                for (int mt = 0; mt < 4; ++mt)
#pragma unroll
                    for (int nt = 0; nt < 4; ++nt)
                        mma_tf32(acc[mt][nt], af[mt], bf[nt]);
            }
        }
        __syncthreads();   // all warps done reading sA

        // ---- epi1: H = tf32(ssp(D + b1)) -> sA ----
#pragma unroll
        for (int mt = 0; mt < 4; ++mt) {
            int row = mr + mt * 16 + g;
#pragma unroll
            for (int nt = 0; nt < 4; ++nt) {
                float* d0 = sA + row * LDK + nc + nt * 8;
                float* d1 = d0 + 8 * LDK;
                d0[pe] = to_tf32(ssp_f(acc[mt][nt][0] + be1[nt]));
                d0[po] = to_tf32(ssp_f(acc[mt][nt][1] + bo1[nt]));
                d1[pe] = to_tf32(ssp_f(acc[mt][nt][2] + be1[nt]));
                d1[po] = to_tf32(ssp_f(acc[mt][nt][3] + bo1[nt]));
            }
        }
        __syncthreads();

        // ================= GEMM2: D = H @ W2t^T =================
#pragma unroll
        for (int mt = 0; mt < 4; ++mt)
#pragma unroll
            for (int nt = 0; nt < 4; ++nt)
#pragma unroll
                for (int q = 0; q < 4; ++q) acc[mt][nt][q] = 0.f;
        {
            const float* pa = sA  + (mr + g) * LDK + 2 * c;
            const float* pb = sB2 + (nc + g) * LDK + 2 * c;
#pragma unroll
            for (int kk = 0; kk < 16; ++kk) {
                const int kb = kk * 8;
                uint32_t af[4][4], bf[4][2];
#pragma unroll
                for (int mt = 0; mt < 4; ++mt) {
                    float2 x = *(const float2*)(pa + mt * 16 * LDK + kb);
                    float2 y = *(const float2*)(pa + (mt * 16 + 8) * LDK + kb);
                    af[mt][0] = __float_as_uint(x.x); af[mt][2] = __float_as_uint(x.y);
                    af[mt][1] = __float_as_uint(y.x); af[mt][3] = __float_as_uint(y.y);
                }
#pragma unroll
                for (int nt = 0; nt < 4; ++nt) {
                    float2 z = *(const float2*)(pb + nt * 8 * LDK + kb);
                    bf[nt][0] = __float_as_uint(z.x); bf[nt][1] = __float_as_uint(z.y);
                }
#pragma unroll
                for (int mt = 0; mt < 4; ++mt)
#pragma unroll
                    for (int nt = 0; nt < 4; ++nt)
                        mma_tf32(acc[mt][nt], af[mt], bf[nt]);
            }
        }
        __syncthreads();

        // ---- epi2a: W = ssp(D + b2) -> sA (full fp32) ----
#pragma unroll
        for (int mt = 0; mt < 4; ++mt) {
            int row = mr + mt * 16 + g;
#pragma unroll
            for (int nt = 0; nt < 4; ++nt) {
                float* d0 = sA + row * LDK + nc + nt * 8;
                float* d1 = d0 + 8 * LDK;
                d0[pe] = ssp_f(acc[mt][nt][0] + be2[nt]);
                d0[po] = ssp_f(acc[mt][nt][1] + bo2[nt]);
                d1[pe] = ssp_f(acc[mt][nt][2] + be2[nt]);
                d1[po] = ssp_f(acc[mt][nt][3] + bo2[nt]);
            }
        }
        __syncthreads();

        // ---- epi2b: msg = W * xf[aj]; run-length reduce over sorted targets ----
        {
            const int col = tid & 127;
            const int pc = (col & ~7) + ((col & 3) << 1) + ((col >> 2) & 1);
            const int r0 = (tid >> 7) * 64;
            float acc1 = 0.f;
            int cur = -1;
#pragma unroll 4
            for (int rr = 0; rr < 64; ++rr) {
                int row = r0 + rr;
                int tgt = s_ti[row];
                float wv = sA[row * LDK + pc];
                float xv = __ldg(&g_xf[(size_t)s_aj[row] * C + col]);
                if (tgt != cur) {
                    if (cur >= 0) atomicAdd(&g_agg[(size_t)cur * C + col], acc1);
                    acc1 = 0.f; cur = tgt;
                }
                acc1 = fmaf(wv, xv, acc1);
            }
            if (cur >= 0) atomicAdd(&g_agg[(size_t)cur * C + col], acc1);
        }
        __syncthreads();
    }
}

// ---------------- transpose W[k][n] -> Wt[n][k] (128x128) ----------------
extern "C" __global__ void k_tr(const float* __restrict__ s, int sel) {
    __shared__ float t[32][33];
    float* d = sel ? g_W2t : g_W1t;
    int bx = blockIdx.x, by = blockIdx.y;
    int x = threadIdx.x, y = threadIdx.y;
#pragma unroll
    for (int i = 0; i < 32; i += 8) t[y + i][x] = s[(by * 32 + y + i) * C + bx * 32 + x];
    __syncthreads();
#pragma unroll
    for (int i = 0; i < 32; i += 8) d[(bx * 32 + y + i) * C + by * 32 + x] = t[x][y + i];
}

// ================= FP32 FMA path for the small atom GEMMs =================
__device__ __forceinline__ void load_w(float* Ws, const float* __restrict__ W) {
    const float4* s = (const float4*)W;
    float4* d = (float4*)Ws;
    int tid = threadIdx.x;
#pragma unroll
    for (int i = 0; i < (C * C / 4) / NT; ++i) d[tid + i * NT] = s[tid + i * NT];
}

__device__ __forceinline__ void load_d(float* Ds, const float* __restrict__ src,
                                       int base_row, int nrow) {
    int tid = threadIdx.x;
#pragma unroll
    for (int it = 0; it < (TM * (C / 4)) / NT; ++it) {
        int idx = tid + it * NT;
        int r = idx >> 5, c4 = idx & 31;
        float4 v = make_float4(0.f, 0.f, 0.f, 0.f);
        int gr = base_row + r;
        if (gr < nrow) v = ((const float4*)src)[gr * (C / 4) + c4];
        float* p = Ds + r * LDD + c4 * 4;
        p[0] = v.x; p[1] = v.y; p[2] = v.z; p[3] = v.w;
    }
}

__device__ __forceinline__ void gemm_128(const float* Ds, const float* Ws,
                                         int rt, int ct, unsigned long long acc[8][4]) {
    const float* dp = Ds + rt * 8 * LDD;
    const float* wp = Ws + ct * 2;
#pragma unroll
    for (int i = 0; i < 8; ++i)
#pragma unroll
        for (int j = 0; j < 4; ++j) acc[i][j] = 0ULL;
#pragma unroll 8
    for (int k = 0; k < C; ++k) {
        unsigned long long b[4];
#pragma unroll
        for (int j = 0; j < 4; ++j)
            b[j] = *(const unsigned long long*)(wp + k * C + j * 32);
#pragma unroll
        for (int i = 0; i < 8; ++i) {
            unsigned int au = __float_as_uint(dp[i * LDD + k]);
            unsigned long long a2;
            asm("mov.b64 %0, {%1, %1};" : "=l"(a2) : "r"(au));
#pragma unroll
            for (int j = 0; j < 4; ++j)
                asm("fma.rn.f32x2 %0, %1, %2, %3;"
                    : "=l"(acc[i][j]) : "l"(a2), "l"(b[j]), "l"(acc[i][j]));
        }
    }
}

__device__ __forceinline__ float2 unpack2(unsigned long long v) {
    unsigned int lo, hi;
    asm("mov.b64 {%0, %1}, %2;" : "=r"(lo), "=r"(hi) : "l"(v));
    return make_float2(__uint_as_float(lo), __uint_as_float(hi));
}

extern "C" __global__ void __launch_bounds__(NT, 1)
k_xf(const float* __restrict__ x, const float* __restrict__ Wi, int na) {
    float* smem = (float*)dynsmem;
    float* Ws = smem;
    float* Ds = smem + C * C;
    int tid = threadIdx.x, rt = tid >> 4, ct = tid & 15;
    int base = blockIdx.x * TM;

#pragma unroll
    for (int it = 0; it < (TM * (C / 4)) / NT; ++it) {
        int idx = tid + it * NT;
        int r = idx >> 5, c4 = idx & 31;
        int gr = base + r;
        if (gr < na) ((float4*)(g_agg + (size_t)gr * C))[c4] = make_float4(0.f, 0.f, 0.f, 0.f);
    }

    load_w(Ws, Wi);
    load_d(Ds, x, base, na);
    __syncthreads();

    unsigned long long acc[8][4];
    gemm_128(Ds, Ws, rt, ct, acc);

#pragma unroll
    for (int i = 0; i < 8; ++i) {
        int r = base + rt * 8 + i;
        if (r < na) {
#pragma unroll
            for (int j = 0; j < 4; ++j) {
                float2 v = unpack2(acc[i][j]);
                *(float2*)(&g_xf[r * C + ct * 2 + j * 32]) = v;
            }
        }
    }
}

extern "C" __global__ void __launch_bounds__(NT, 1)
k_out(const float* __restrict__ x,
      const float* __restrict__ Wo, const float* __restrict__ bo,
      const float* __restrict__ Wd, const float* __restrict__ bd,
      float* __restrict__ out_y, float* __restrict__ out_v, int na) {
    float* smem = (float*)dynsmem;
    float* Ws = smem;
    float* Ds = smem + C * C;
    float* Hs = Ds + TM * LDD;
    int tid = threadIdx.x, rt = tid >> 4, ct = tid & 15;
    int base = blockIdx.x * TM;

    float bov[8], bdv[8];
#pragma unroll
    for (int j = 0; j < 4; ++j) {
        int c0 = ct * 2 + j * 32;
        bov[2 * j] = bo[c0]; bov[2 * j + 1] = bo[c0 + 1];
        bdv[2 * j] = bd[c0]; bdv[2 * j + 1] = bd[c0 + 1];
    }

    load_w(Ws, Wo);
    load_d(Ds, g_agg, base, na);
    __syncthreads();

    unsigned long long acc[8][4];
    gemm_128(Ds, Ws, rt, ct, acc);

#pragma unroll
    for (int i = 0; i < 8; ++i) {
#pragma unroll
        for (int j = 0; j < 4; ++j) {
            float2 v = unpack2(acc[i][j]);
            v.x = ssp_f(v.x + bov[2 * j]);
            v.y = ssp_f(v.y + bov[2 * j + 1]);
            *(float2*)(&Hs[(rt * 8 + i) * LDD + ct * 2 + j * 32]) = v;
        }
    }
    __syncthreads();

    load_w(Ws, Wd);
    __syncthreads();

    gemm_128(Hs, Ws, rt, ct, acc);

#pragma unroll
    for (int i = 0; i < 8; ++i) {
        int r = base + rt * 8 + i;
        if (r < na) {
#pragma unroll
            for (int j = 0; j < 4; ++j) {
                int c0 = ct * 2 + j * 32;
                float2 v = unpack2(acc[i][j]);
                v.x += bdv[2 * j];
                v.y += bdv[2 * j + 1];
                float2 xv = *(const float2*)(&x[(size_t)r * C + c0]);
                *(float2*)(&out_v[(size_t)r * C + c0]) = v;
                *(float2*)(&out_y[(size_t)r * C + c0]) = make_float2(xv.x + v.x, xv.y + v.y);
            }
        }
    }
}

// ============================ launch ============================
extern "C" void kernel_launch(void* const* d_in, const int* in_sizes, int n_in,
                              void* d_out, int out_size) {
    const float* x    = (const float*)d_in[0];
    const float* dijk = (const float*)d_in[1];
    const int*   idxj = (const int*)d_in[2];
    const int*   segi = (const int*)d_in[3];
    const int*   segj = (const int*)d_in[4];
    const float* W1   = (const float*)d_in[5];
    const float* b1   = (const float*)d_in[6];
    const float* W2   = (const float*)d_in[7];
    const float* b2   = (const float*)d_in[8];
    const float* Wi   = (const float*)d_in[9];
    const float* Wo   = (const float*)d_in[10];
    const float* bo   = (const float*)d_in[11];
    const float* Wd   = (const float*)d_in[12];
    const float* bd   = (const float*)d_in[13];

    int na = in_sizes[0] / C;
    int ne = in_sizes[2];
    int ntiles = (ne + TM - 1) / TM;

    float* out_y = (float*)d_out;
    float* out_v = out_y + (size_t)na * C;

    const int SMEM_XF   = (C * C + TM * LDD) * 4;
    const int SMEM_OUT  = (C * C + 2 * TM * LDD) * 4;
    const int SMEM_EDGE = 3 * 128 * LDK * 4 + 2 * TM * 4;   // 203776

    cudaFuncSetAttribute(k_xf,        cudaFuncAttributeMaxDynamicSharedMemorySize, SMEM_XF);
    cudaFuncSetAttribute(k_out,       cudaFuncAttributeMaxDynamicSharedMemorySize, SMEM_OUT);
    cudaFuncSetAttribute(k_edges_mma, cudaFuncAttributeMaxDynamicSharedMemorySize, SMEM_EDGE);

    int g_atoms = (na + TM - 1) / TM;

    k_tr<<<dim3(4, 4), dim3(32, 8)>>>(W1, 0);
    k_tr<<<dim3(4, 4), dim3(32, 8)>>>(W2, 1);
    k_xf<<<g_atoms, NT, SMEM_XF>>>(x, Wi, na);
    k_edges_mma<<<148, NT, SMEM_EDGE>>>(dijk, idxj, segi, segj, b1, b2, ne, ntiles);
    k_out<<<g_atoms, NT, SMEM_OUT>>>(x, Wo, bo, Wd, bd, out_y, out_v, na);
}

// round 6
// speedup vs baseline: 1.6616x; 1.0463x over previous
#include <cuda_runtime.h>
#include <cstdint>

#define C   128
#define LDD 130   // FMA-path pad
#define LDK 132   // mma-path smem row stride (floats)
#define TM  128
#define NT  256   // FMA-path threads
#define NTE 512   // edge-kernel threads (16 warps)

extern __shared__ char dynsmem[];

// ---------------- scratch (device globals; allocation-free rule) ----------------
static __device__ __align__(16) float g_xf[20480 * C];
static __device__ __align__(16) float g_agg[20480 * C];
static __device__ __align__(16) float g_W1t[C * C];
static __device__ __align__(16) float g_W2t[C * C];

__device__ __forceinline__ float ssp_f(float x) {
    float t = __expf(-fabsf(x));
    return fmaxf(x, 0.0f) + __logf(1.0f + t) - 0.693147180559945f;
}

__device__ __forceinline__ float to_tf32(float x) {
    uint32_t u;
    asm("cvt.rna.tf32.f32 %0, %1;" : "=r"(u) : "f"(x));
    return __uint_as_float(u);
}

__device__ __forceinline__ void mma_tf32(float* d, const uint32_t* a, const uint32_t* b) {
    asm volatile(
        "mma.sync.aligned.m16n8k8.row.col.f32.tf32.tf32.f32 "
        "{%0,%1,%2,%3}, {%4,%5,%6,%7}, {%8,%9}, {%0,%1,%2,%3};"
        : "+f"(d[0]), "+f"(d[1]), "+f"(d[2]), "+f"(d[3])
        : "r"(a[0]), "r"(a[1]), "r"(a[2]), "r"(a[3]), "r"(b[0]), "r"(b[1]));
}

// =====================================================================
// Edge kernel (mma.sync tf32, 16 warps): agg += scatter(ssp(ssp(dijk@W1+b1)@W2+b2)*xf[idx_j])
// SMEM tiles row-major, LDK floats/row, octet k-interleave:
// logical k j8 -> phys ((j8&3)<<1)|(j8>>2) so each fragment pair is one LDS.64.
// =====================================================================

extern "C" __global__ void __launch_bounds__(NTE, 1)
k_edges_mma(const float* __restrict__ dijk,
            const int* __restrict__ idx_j,
            const int* __restrict__ seg_i,
            const int* __restrict__ seg_j,
            const float* __restrict__ b1, const float* __restrict__ b2,
            int ne, int ntiles) {
    float* sA  = (float*)dynsmem;                 // 128 x LDK  (A / H / W tile)
    float* sB1 = sA + 128 * LDK;                  // W1t
    float* sB2 = sB1 + 128 * LDK;                 // W2t
    int* s_aj = (int*)(sB2 + 128 * LDK);
    int* s_ti = s_aj + TM;

    const int tid = threadIdx.x;
    const int wid = tid >> 5, lane = tid & 31;
    const int g = lane >> 2, c = lane & 3;
    const int mr = (wid & 3) * 32;                // warp row-block (32 rows)
    const int nc = (wid >> 2) * 32;               // warp col-block (32 cols)
    const int pe = ((c & 1) << 2) + (c >> 1);     // phys pos of logical col 2c within octet
    const int po = pe + 2;

    // per-thread bias registers for the 8 columns this thread owns (per n-tile)
    float be1[4], bo1[4], be2[4], bo2[4];
#pragma unroll
    for (int nt = 0; nt < 4; ++nt) {
        int col = nc + nt * 8 + 2 * c;
        be1[nt] = b1[col]; bo1[nt] = b1[col + 1];
        be2[nt] = b2[col]; bo2[nt] = b2[col + 1];
    }

    // load W1t, W2t into SMEM (tf32-rounded, interleaved layout)
#pragma unroll
    for (int i = 0; i < 8; ++i) {
        int wg = wid + (i << 4);                  // 0..127
        int row = (wg & 15) * 8 + ((lane >> 2) & 7);
        int c4  = (wg >> 4) * 4 + (lane & 3);
        float4 v1 = ((const float4*)g_W1t)[row * 32 + c4];
        float4 v2 = ((const float4*)g_W2t)[row * 32 + c4];
        float* d1 = sB1 + row * LDK + (c4 >> 1) * 8 + (c4 & 1);
        float* d2 = sB2 + row * LDK + (c4 >> 1) * 8 + (c4 & 1);
        d1[0] = to_tf32(v1.x); d1[2] = to_tf32(v1.y); d1[4] = to_tf32(v1.z); d1[6] = to_tf32(v1.w);
        d2[0] = to_tf32(v2.x); d2[2] = to_tf32(v2.y); d2[4] = to_tf32(v2.z); d2[6] = to_tf32(v2.w);
    }
    __syncthreads();

    for (int t = blockIdx.x; t < ntiles; t += gridDim.x) {
        const int base = t * TM;

        if (tid < TM) {
            int e = base + tid, aj = 0, ti = -1;
            if (e < ne) { int p = seg_j[e]; aj = idx_j[p]; ti = seg_i[p]; }
            s_aj[tid] = aj; s_ti[tid] = ti;
        }
        // ---- load + tf32-round A tile (dijk rows) ----
#pragma unroll
        for (int i = 0; i < 8; ++i) {
            int wg = wid + (i << 4);
            int row = (wg & 15) * 8 + ((lane >> 2) & 7);
            int c4  = (wg >> 4) * 4 + (lane & 3);
            float4 v = make_float4(0.f, 0.f, 0.f, 0.f);
            int gr = base + row;
            if (gr < ne) v = ((const float4*)dijk)[gr * 32 + c4];
            float* d = sA + row * LDK + (c4 >> 1) * 8 + (c4 & 1);
            d[0] = to_tf32(v.x); d[2] = to_tf32(v.y); d[4] = to_tf32(v.z); d[6] = to_tf32(v.w);
        }
        __syncthreads();

        // ================= GEMM1: D = A @ W1t^T =================
        float acc[2][4][4];
#pragma unroll
        for (int mt = 0; mt < 2; ++mt)
#pragma unroll
            for (int nt = 0; nt < 4; ++nt)
#pragma unroll
                for (int q = 0; q < 4; ++q) acc[mt][nt][q] = 0.f;
        {
            const float* pa = sA  + (mr + g) * LDK + 2 * c;
            const float* pb = sB1 + (nc + g) * LDK + 2 * c;
#pragma unroll
            for (int kk = 0; kk < 16; ++kk) {
                const int kb = kk * 8;
                uint32_t af[2][4], bf[4][2];
#pragma unroll
                for (int mt = 0; mt < 2; ++mt) {
                    float2 x = *(const float2*)(pa + mt * 16 * LDK + kb);
                    float2 y = *(const float2*)(pa + (mt * 16 + 8) * LDK + kb);
                    af[mt][0] = __float_as_uint(x.x); af[mt][2] = __float_as_uint(x.y);
                    af[mt][1] = __float_as_uint(y.x); af[mt][3] = __float_as_uint(y.y);
                }
#pragma unroll
                for (int nt = 0; nt < 4; ++nt) {
                    float2 z = *(const float2*)(pb + nt * 8 * LDK + kb);
                    bf[nt][0] = __float_as_uint(z.x); bf[nt][1] = __float_as_uint(z.y);
                }
#pragma unroll
                for (int mt = 0; mt < 2; ++mt)
#pragma unroll
                    for (int nt = 0; nt < 4; ++nt)
                        mma_tf32(acc[mt][nt], af[mt], bf[nt]);
            }
        }
        __syncthreads();   // all warps done reading sA

        // ---- epi1: H = tf32(ssp(D + b1)) -> sA ----
#pragma unroll
        for (int mt = 0; mt < 2; ++mt) {
            int row = mr + mt * 16 + g;
#pragma unroll
            for (int nt = 0; nt < 4; ++nt) {
                float* d0 = sA + row * LDK + nc + nt * 8;
                float* d1 = d0 + 8 * LDK;
                d0[pe] = to_tf32(ssp_f(acc[mt][nt][0] + be1[nt]));
                d0[po] = to_tf32(ssp_f(acc[mt][nt][1] + bo1[nt]));
                d1[pe] = to_tf32(ssp_f(acc[mt][nt][2] + be1[nt]));
                d1[po] = to_tf32(ssp_f(acc[mt][nt][3] + bo1[nt]));
            }
        }
        __syncthreads();

        // ================= GEMM2: D = H @ W2t^T =================
#pragma unroll
        for (int mt = 0; mt < 2; ++mt)
#pragma unroll
            for (int nt = 0; nt < 4; ++nt)
#pragma unroll
                for (int q = 0; q < 4; ++q) acc[mt][nt][q] = 0.f;
        {
            const float* pa = sA  + (mr + g) * LDK + 2 * c;
            const float* pb = sB2 + (nc + g) * LDK + 2 * c;
#pragma unroll
            for (int kk = 0; kk < 16; ++kk) {
                const int kb = kk * 8;
                uint32_t af[2][4], bf[4][2];
#pragma unroll
                for (int mt = 0; mt < 2; ++mt) {
                    float2 x = *(const float2*)(pa + mt * 16 * LDK + kb);
                    float2 y = *(const float2*)(pa + (mt * 16 + 8) * LDK + kb);
                    af[mt][0] = __float_as_uint(x.x); af[mt][2] = __float_as_uint(x.y);
                    af[mt][1] = __float_as_uint(y.x); af[mt][3] = __float_as_uint(y.y);
                }
#pragma unroll
                for (int nt = 0; nt < 4; ++nt) {
                    float2 z = *(const float2*)(pb + nt * 8 * LDK + kb);
                    bf[nt][0] = __float_as_uint(z.x); bf[nt][1] = __float_as_uint(z.y);
                }
#pragma unroll
                for (int mt = 0; mt < 2; ++mt)
#pragma unroll
                    for (int nt = 0; nt < 4; ++nt)
                        mma_tf32(acc[mt][nt], af[mt], bf[nt]);
            }
        }
        __syncthreads();

        // ---- epi2a: W = ssp(D + b2) -> sA (full fp32) ----
#pragma unroll
        for (int mt = 0; mt < 2; ++mt) {
            int row = mr + mt * 16 + g;
#pragma unroll
            for (int nt = 0; nt < 4; ++nt) {
                float* d0 = sA + row * LDK + nc + nt * 8;
                float* d1 = d0 + 8 * LDK;
                d0[pe] = ssp_f(acc[mt][nt][0] + be2[nt]);
                d0[po] = ssp_f(acc[mt][nt][1] + bo2[nt]);
                d1[pe] = ssp_f(acc[mt][nt][2] + be2[nt]);
                d1[po] = ssp_f(acc[mt][nt][3] + bo2[nt]);
            }
        }
        __syncthreads();

        // ---- epi2b: msg = W * xf[aj]; run-length reduce over sorted targets ----
        {
            const int col = tid & 127;
            const int pc = (col & ~7) + ((col & 3) << 1) + ((col >> 2) & 1);
            const int r0 = (tid >> 7) * 32;
            float acc1 = 0.f;
            int cur = -1;
#pragma unroll 4
            for (int rr = 0; rr < 32; ++rr) {
                int row = r0 + rr;
                int tgt = s_ti[row];
                float wv = sA[row * LDK + pc];
                float xv = __ldg(&g_xf[(size_t)s_aj[row] * C + col]);
                if (tgt != cur) {
                    if (cur >= 0) atomicAdd(&g_agg[(size_t)cur * C + col], acc1);
                    acc1 = 0.f; cur = tgt;
                }
                acc1 = fmaf(wv, xv, acc1);
            }
            if (cur >= 0) atomicAdd(&g_agg[(size_t)cur * C + col], acc1);
        }
        __syncthreads();
    }
}

// ---------------- transpose W[k][n] -> Wt[n][k] (128x128) ----------------
extern "C" __global__ void k_tr(const float* __restrict__ s, int sel) {
    __shared__ float t[32][33];
    float* d = sel ? g_W2t : g_W1t;
    int bx = blockIdx.x, by = blockIdx.y;
    int x = threadIdx.x, y = threadIdx.y;
#pragma unroll
    for (int i = 0; i < 32; i += 8) t[y + i][x] = s[(by * 32 + y + i) * C + bx * 32 + x];
    __syncthreads();
#pragma unroll
    for (int i = 0; i < 32; i += 8) d[(bx * 32 + y + i) * C + by * 32 + x] = t[x][y + i];
}

// ================= FP32 FMA path for the small atom GEMMs =================
__device__ __forceinline__ void load_w(float* Ws, const float* __restrict__ W) {
    const float4* s = (const float4*)W;
    float4* d = (float4*)Ws;
    int tid = threadIdx.x;
#pragma unroll
    for (int i = 0; i < (C * C / 4) / NT; ++i) d[tid + i * NT] = s[tid + i * NT];
}

__device__ __forceinline__ void load_d(float* Ds, const float* __restrict__ src,
                                       int base_row, int nrow) {
    int tid = threadIdx.x;
#pragma unroll
    for (int it = 0; it < (TM * (C / 4)) / NT; ++it) {
        int idx = tid + it * NT;
        int r = idx >> 5, c4 = idx & 31;
        float4 v = make_float4(0.f, 0.f, 0.f, 0.f);
        int gr = base_row + r;
        if (gr < nrow) v = ((const float4*)src)[gr * (C / 4) + c4];
        float* p = Ds + r * LDD + c4 * 4;
        p[0] = v.x; p[1] = v.y; p[2] = v.z; p[3] = v.w;
    }
}

__device__ __forceinline__ void gemm_128(const float* Ds, const float* Ws,
                                         int rt, int ct, unsigned long long acc[8][4]) {
    const float* dp = Ds + rt * 8 * LDD;
    const float* wp = Ws + ct * 2;
#pragma unroll
    for (int i = 0; i < 8; ++i)
#pragma unroll
        for (int j = 0; j < 4; ++j) acc[i][j] = 0ULL;
#pragma unroll 8
    for (int k = 0; k < C; ++k) {
        unsigned long long b[4];
#pragma unroll
        for (int j = 0; j < 4; ++j)
            b[j] = *(const unsigned long long*)(wp + k * C + j * 32);
#pragma unroll
        for (int i = 0; i < 8; ++i) {
            unsigned int au = __float_as_uint(dp[i * LDD + k]);
            unsigned long long a2;
            asm("mov.b64 %0, {%1, %1};" : "=l"(a2) : "r"(au));
#pragma unroll
            for (int j = 0; j < 4; ++j)
                asm("fma.rn.f32x2 %0, %1, %2, %3;"
                    : "=l"(acc[i][j]) : "l"(a2), "l"(b[j]), "l"(acc[i][j]));
        }
    }
}

__device__ __forceinline__ float2 unpack2(unsigned long long v) {
    unsigned int lo, hi;
    asm("mov.b64 {%0, %1}, %2;" : "=r"(lo), "=r"(hi) : "l"(v));
    return make_float2(__uint_as_float(lo), __uint_as_float(hi));
}

extern "C" __global__ void __launch_bounds__(NT, 1)
k_xf(const float* __restrict__ x, const float* __restrict__ Wi, int na) {
    float* smem = (float*)dynsmem;
    float* Ws = smem;
    float* Ds = smem + C * C;
    int tid = threadIdx.x, rt = tid >> 4, ct = tid & 15;
    int base = blockIdx.x * TM;

#pragma unroll
    for (int it = 0; it < (TM * (C / 4)) / NT; ++it) {
        int idx = tid + it * NT;
        int r = idx >> 5, c4 = idx & 31;
        int gr = base + r;
        if (gr < na) ((float4*)(g_agg + (size_t)gr * C))[c4] = make_float4(0.f, 0.f, 0.f, 0.f);
    }

    load_w(Ws, Wi);
    load_d(Ds, x, base, na);
    __syncthreads();

    unsigned long long acc[8][4];
    gemm_128(Ds, Ws, rt, ct, acc);

#pragma unroll
    for (int i = 0; i < 8; ++i) {
        int r = base + rt * 8 + i;
        if (r < na) {
#pragma unroll
            for (int j = 0; j < 4; ++j) {
                float2 v = unpack2(acc[i][j]);
                *(float2*)(&g_xf[r * C + ct * 2 + j * 32]) = v;
            }
        }
    }
}

extern "C" __global__ void __launch_bounds__(NT, 1)
k_out(const float* __restrict__ x,
      const float* __restrict__ Wo, const float* __restrict__ bo,
      const float* __restrict__ Wd, const float* __restrict__ bd,
      float* __restrict__ out_y, float* __restrict__ out_v, int na) {
    float* smem = (float*)dynsmem;
    float* Ws = smem;
    float* Ds = smem + C * C;
    float* Hs = Ds + TM * LDD;
    int tid = threadIdx.x, rt = tid >> 4, ct = tid & 15;
    int base = blockIdx.x * TM;

    float bov[8], bdv[8];
#pragma unroll
    for (int j = 0; j < 4; ++j) {
        int c0 = ct * 2 + j * 32;
        bov[2 * j] = bo[c0]; bov[2 * j + 1] = bo[c0 + 1];
        bdv[2 * j] = bd[c0]; bdv[2 * j + 1] = bd[c0 + 1];
    }

    load_w(Ws, Wo);
    load_d(Ds, g_agg, base, na);
    __syncthreads();

    unsigned long long acc[8][4];
    gemm_128(Ds, Ws, rt, ct, acc);

#pragma unroll
    for (int i = 0; i < 8; ++i) {
#pragma unroll
        for (int j = 0; j < 4; ++j) {
            float2 v = unpack2(acc[i][j]);
            v.x = ssp_f(v.x + bov[2 * j]);
            v.y = ssp_f(v.y + bov[2 * j + 1]);
            *(float2*)(&Hs[(rt * 8 + i) * LDD + ct * 2 + j * 32]) = v;
        }
    }
    __syncthreads();

    load_w(Ws, Wd);
    __syncthreads();

    gemm_128(Hs, Ws, rt, ct, acc);

#pragma unroll
    for (int i = 0; i < 8; ++i) {
        int r = base + rt * 8 + i;
        if (r < na) {
#pragma unroll
            for (int j = 0; j < 4; ++j) {
                int c0 = ct * 2 + j * 32;
                float2 v = unpack2(acc[i][j]);
                v.x += bdv[2 * j];
                v.y += bdv[2 * j + 1];
                float2 xv = *(const float2*)(&x[(size_t)r * C + c0]);
                *(float2*)(&out_v[(size_t)r * C + c0]) = v;
                *(float2*)(&out_y[(size_t)r * C + c0]) = make_float2(xv.x + v.x, xv.y + v.y);
            }
        }
    }
}

// ============================ launch ============================
extern "C" void kernel_launch(void* const* d_in, const int* in_sizes, int n_in,
                              void* d_out, int out_size) {
    const float* x    = (const float*)d_in[0];
    const float* dijk = (const float*)d_in[1];
    const int*   idxj = (const int*)d_in[2];
    const int*   segi = (const int*)d_in[3];
    const int*   segj = (const int*)d_in[4];
    const float* W1   = (const float*)d_in[5];
    const float* b1   = (const float*)d_in[6];
    const float* W2   = (const float*)d_in[7];
    const float* b2   = (const float*)d_in[8];
    const float* Wi   = (const float*)d_in[9];
    const float* Wo   = (const float*)d_in[10];
    const float* bo   = (const float*)d_in[11];
    const float* Wd   = (const float*)d_in[12];
    const float* bd   = (const float*)d_in[13];

    int na = in_sizes[0] / C;
    int ne = in_sizes[2];
    int ntiles = (ne + TM - 1) / TM;

    float* out_y = (float*)d_out;
    float* out_v = out_y + (size_t)na * C;

    const int SMEM_XF   = (C * C + TM * LDD) * 4;
    const int SMEM_OUT  = (C * C + 2 * TM * LDD) * 4;
    const int SMEM_EDGE = 3 * 128 * LDK * 4 + 2 * TM * 4;   // 203776

    cudaFuncSetAttribute(k_xf,        cudaFuncAttributeMaxDynamicSharedMemorySize, SMEM_XF);
    cudaFuncSetAttribute(k_out,       cudaFuncAttributeMaxDynamicSharedMemorySize, SMEM_OUT);
    cudaFuncSetAttribute(k_edges_mma, cudaFuncAttributeMaxDynamicSharedMemorySize, SMEM_EDGE);

    int g_atoms = (na + TM - 1) / TM;

    k_tr<<<dim3(4, 4), dim3(32, 8)>>>(W1, 0);
    k_tr<<<dim3(4, 4), dim3(32, 8)>>>(W2, 1);
    k_xf<<<g_atoms, NT, SMEM_XF>>>(x, Wi, na);
    k_edges_mma<<<148, NTE, SMEM_EDGE>>>(dijk, idxj, segi, segj, b1, b2, ne, ntiles);
    k_out<<<g_atoms, NT, SMEM_OUT>>>(x, Wo, bo, Wd, bd, out_y, out_v, na);
}

// round 7
// speedup vs baseline: 1.9488x; 1.1728x over previous
#include <cuda_runtime.h>
#include <cstdint>

#define C   128
#define LDD 130   // FMA-path pad
#define LDK 136   // mma-path smem row stride (floats): 8-bank row stride => conflict-free LDS.64
#define TM  128
#define NT  256   // FMA-path threads
#define NTE 512   // edge-kernel threads (16 warps)

extern __shared__ char dynsmem[];

// ---------------- scratch (device globals; allocation-free rule) ----------------
static __device__ __align__(16) float g_xf[20480 * C];
static __device__ __align__(16) float g_agg[20480 * C];
static __device__ __align__(16) float g_W1t[C * C];
static __device__ __align__(16) float g_W2t[C * C];

__device__ __forceinline__ float ssp_f(float x) {
    float t = __expf(-fabsf(x));
    return fmaxf(x, 0.0f) + __logf(1.0f + t) - 0.693147180559945f;
}

__device__ __forceinline__ float to_tf32(float x) {
    uint32_t u;
    asm("cvt.rna.tf32.f32 %0, %1;" : "=r"(u) : "f"(x));
    return __uint_as_float(u);
}

__device__ __forceinline__ void mma_tf32(float* d, const uint32_t* a, const uint32_t* b) {
    asm volatile(
        "mma.sync.aligned.m16n8k8.row.col.f32.tf32.tf32.f32 "
        "{%0,%1,%2,%3}, {%4,%5,%6,%7}, {%8,%9}, {%0,%1,%2,%3};"
        : "+f"(d[0]), "+f"(d[1]), "+f"(d[2]), "+f"(d[3])
        : "r"(a[0]), "r"(a[1]), "r"(a[2]), "r"(a[3]), "r"(b[0]), "r"(b[1]));
}

// =====================================================================
// Edge kernel (mma.sync tf32, 16 warps): agg += scatter(ssp(ssp(dijk@W1+b1)@W2+b2)*xf[idx_j])
// SMEM tiles row-major, LDK floats/row, octet k-interleave:
// logical k j8 -> phys ((j8&3)<<1)|(j8>>2) so each fragment pair {k, k+4} is one LDS.64.
// =====================================================================

extern "C" __global__ void __launch_bounds__(NTE, 1)
k_edges_mma(const float* __restrict__ dijk,
            const int* __restrict__ idx_j,
            const int* __restrict__ seg_i,
            const int* __restrict__ seg_j,
            const float* __restrict__ b1, const float* __restrict__ b2,
            int ne, int ntiles) {
    float* sA  = (float*)dynsmem;                 // 128 x LDK  (A / H / W tile)
    float* sB1 = sA + 128 * LDK;                  // W1t
    float* sB2 = sB1 + 128 * LDK;                 // W2t
    int* s_aj = (int*)(sB2 + 128 * LDK);
    int* s_ti = s_aj + TM;

    const int tid = threadIdx.x;
    const int wid = tid >> 5, lane = tid & 31;
    const int g = lane >> 2, c = lane & 3;
    const int mr = (wid & 3) * 32;                // warp row-block (32 rows)
    const int nc = (wid >> 2) * 32;               // warp col-block (32 cols)
    const int pe = ((c & 1) << 2) + (c >> 1);     // phys pos of logical col 2c within octet
    const int po = pe + 2;

    // per-thread bias registers for the 8 columns this thread owns (per n-tile)
    float be1[4], bo1[4], be2[4], bo2[4];
#pragma unroll
    for (int nt = 0; nt < 4; ++nt) {
        int col = nc + nt * 8 + 2 * c;
        be1[nt] = b1[col]; bo1[nt] = b1[col + 1];
        be2[nt] = b2[col]; bo2[nt] = b2[col + 1];
    }

    // load W1t, W2t into SMEM (tf32-rounded, interleaved layout)
#pragma unroll
    for (int i = 0; i < 8; ++i) {
        int wg = wid + (i << 4);                  // 0..127
        int row = (wg & 15) * 8 + ((lane >> 2) & 7);
        int c4  = (wg >> 4) * 4 + (lane & 3);
        float4 v1 = ((const float4*)g_W1t)[row * 32 + c4];
        float4 v2 = ((const float4*)g_W2t)[row * 32 + c4];
        float* d1 = sB1 + row * LDK + (c4 >> 1) * 8 + (c4 & 1);
        float* d2 = sB2 + row * LDK + (c4 >> 1) * 8 + (c4 & 1);
        d1[0] = to_tf32(v1.x); d1[2] = to_tf32(v1.y); d1[4] = to_tf32(v1.z); d1[6] = to_tf32(v1.w);
        d2[0] = to_tf32(v2.x); d2[2] = to_tf32(v2.y); d2[4] = to_tf32(v2.z); d2[6] = to_tf32(v2.w);
    }
    __syncthreads();

    for (int t = blockIdx.x; t < ntiles; t += gridDim.x) {
        const int base = t * TM;

        if (tid < TM) {
            int e = base + tid, aj = 0, ti = -1;
            if (e < ne) { int p = seg_j[e]; aj = idx_j[p]; ti = seg_i[p]; }
            s_aj[tid] = aj; s_ti[tid] = ti;
        }
        // ---- load + tf32-round A tile (dijk rows) ----
#pragma unroll
        for (int i = 0; i < 8; ++i) {
            int wg = wid + (i << 4);
            int row = (wg & 15) * 8 + ((lane >> 2) & 7);
            int c4  = (wg >> 4) * 4 + (lane & 3);
            float4 v = make_float4(0.f, 0.f, 0.f, 0.f);
            int gr = base + row;
            if (gr < ne) v = ((const float4*)dijk)[gr * 32 + c4];
            float* d = sA + row * LDK + (c4 >> 1) * 8 + (c4 & 1);
            d[0] = to_tf32(v.x); d[2] = to_tf32(v.y); d[4] = to_tf32(v.z); d[6] = to_tf32(v.w);
        }
        __syncthreads();

        // ================= GEMM1: D = A @ W1t^T =================
        float acc[2][4][4];
#pragma unroll
        for (int mt = 0; mt < 2; ++mt)
#pragma unroll
            for (int nt = 0; nt < 4; ++nt)
#pragma unroll
                for (int q = 0; q < 4; ++q) acc[mt][nt][q] = 0.f;
        {
            const float* pa = sA  + (mr + g) * LDK + 2 * c;
            const float* pb = sB1 + (nc + g) * LDK + 2 * c;
#pragma unroll
            for (int kk = 0; kk < 16; ++kk) {
                const int kb = kk * 8;
                uint32_t af[2][4], bf[4][2];
#pragma unroll
                for (int mt = 0; mt < 2; ++mt) {
                    float2 x = *(const float2*)(pa + mt * 16 * LDK + kb);
                    float2 y = *(const float2*)(pa + (mt * 16 + 8) * LDK + kb);
                    af[mt][0] = __float_as_uint(x.x); af[mt][2] = __float_as_uint(x.y);
                    af[mt][1] = __float_as_uint(y.x); af[mt][3] = __float_as_uint(y.y);
                }
#pragma unroll
                for (int nt = 0; nt < 4; ++nt) {
                    float2 z = *(const float2*)(pb + nt * 8 * LDK + kb);
                    bf[nt][0] = __float_as_uint(z.x); bf[nt][1] = __float_as_uint(z.y);
                }
#pragma unroll
                for (int mt = 0; mt < 2; ++mt)
#pragma unroll
                    for (int nt = 0; nt < 4; ++nt)
                        mma_tf32(acc[mt][nt], af[mt], bf[nt]);
            }
        }
        __syncthreads();   // all warps done reading sA

        // ---- epi1: H = tf32(ssp(D + b1)) -> sA ----
#pragma unroll
        for (int mt = 0; mt < 2; ++mt) {
            int row = mr + mt * 16 + g;
#pragma unroll
            for (int nt = 0; nt < 4; ++nt) {
                float* d0 = sA + row * LDK + nc + nt * 8;
                float* d1 = d0 + 8 * LDK;
                d0[pe] = to_tf32(ssp_f(acc[mt][nt][0] + be1[nt]));
                d0[po] = to_tf32(ssp_f(acc[mt][nt][1] + bo1[nt]));
                d1[pe] = to_tf32(ssp_f(acc[mt][nt][2] + be1[nt]));
                d1[po] = to_tf32(ssp_f(acc[mt][nt][3] + bo1[nt]));
            }
        }
        __syncthreads();

        // ================= GEMM2: D = H @ W2t^T =================
#pragma unroll
        for (int mt = 0; mt < 2; ++mt)
#pragma unroll
            for (int nt = 0; nt < 4; ++nt)
#pragma unroll
                for (int q = 0; q < 4; ++q) acc[mt][nt][q] = 0.f;
        {
            const float* pa = sA  + (mr + g) * LDK + 2 * c;
            const float* pb = sB2 + (nc + g) * LDK + 2 * c;
#pragma unroll
            for (int kk = 0; kk < 16; ++kk) {
                const int kb = kk * 8;
                uint32_t af[2][4], bf[4][2];
#pragma unroll
                for (int mt = 0; mt < 2; ++mt) {
                    float2 x = *(const float2*)(pa + mt * 16 * LDK + kb);
                    float2 y = *(const float2*)(pa + (mt * 16 + 8) * LDK + kb);
                    af[mt][0] = __float_as_uint(x.x); af[mt][2] = __float_as_uint(x.y);
                    af[mt][1] = __float_as_uint(y.x); af[mt][3] = __float_as_uint(y.y);
                }
#pragma unroll
                for (int nt = 0; nt < 4; ++nt) {
                    float2 z = *(const float2*)(pb + nt * 8 * LDK + kb);
                    bf[nt][0] = __float_as_uint(z.x); bf[nt][1] = __float_as_uint(z.y);
                }
#pragma unroll
                for (int mt = 0; mt < 2; ++mt)
#pragma unroll
                    for (int nt = 0; nt < 4; ++nt)
                        mma_tf32(acc[mt][nt], af[mt], bf[nt]);
            }
        }
        __syncthreads();

        // ---- epi2a: W = ssp(D + b2) -> sA (full fp32) ----
#pragma unroll
        for (int mt = 0; mt < 2; ++mt) {
            int row = mr + mt * 16 + g;
#pragma unroll
            for (int nt = 0; nt < 4; ++nt) {
                float* d0 = sA + row * LDK + nc + nt * 8;
                float* d1 = d0 + 8 * LDK;
                d0[pe] = ssp_f(acc[mt][nt][0] + be2[nt]);
                d0[po] = ssp_f(acc[mt][nt][1] + bo2[nt]);
                d1[pe] = ssp_f(acc[mt][nt][2] + be2[nt]);
                d1[po] = ssp_f(acc[mt][nt][3] + bo2[nt]);
            }
        }
        __syncthreads();

        // ---- epi2b: msg = W * xf[aj]; run-length reduce over sorted targets ----
        {
            const int col = tid & 127;
            const int pc = (col & ~7) + ((col & 3) << 1) + ((col >> 2) & 1);
            const int r0 = (tid >> 7) * 32;
            float acc1 = 0.f;
            int cur = -1;
#pragma unroll 4
            for (int rr = 0; rr < 32; ++rr) {
                int row = r0 + rr;
                int tgt = s_ti[row];
                float wv = sA[row * LDK + pc];
                float xv = __ldg(&g_xf[(size_t)s_aj[row] * C + col]);
                if (tgt != cur) {
                    if (cur >= 0) atomicAdd(&g_agg[(size_t)cur * C + col], acc1);
                    acc1 = 0.f; cur = tgt;
                }
                acc1 = fmaf(wv, xv, acc1);
            }
            if (cur >= 0) atomicAdd(&g_agg[(size_t)cur * C + col], acc1);
        }
        __syncthreads();
    }
}

// ---------------- transpose W[k][n] -> Wt[n][k] (128x128) ----------------
extern "C" __global__ void k_tr(const float* __restrict__ s, int sel) {
    __shared__ float t[32][33];
    float* d = sel ? g_W2t : g_W1t;
    int bx = blockIdx.x, by = blockIdx.y;
    int x = threadIdx.x, y = threadIdx.y;
#pragma unroll
    for (int i = 0; i < 32; i += 8) t[y + i][x] = s[(by * 32 + y + i) * C + bx * 32 + x];
    __syncthreads();
#pragma unroll
    for (int i = 0; i < 32; i += 8) d[(bx * 32 + y + i) * C + by * 32 + x] = t[x][y + i];
}

// ================= FP32 FMA path for the small atom GEMMs =================
__device__ __forceinline__ void load_w(float* Ws, const float* __restrict__ W) {
    const float4* s = (const float4*)W;
    float4* d = (float4*)Ws;
    int tid = threadIdx.x;
#pragma unroll
    for (int i = 0; i < (C * C / 4) / NT; ++i) d[tid + i * NT] = s[tid + i * NT];
}

__device__ __forceinline__ void load_d(float* Ds, const float* __restrict__ src,
                                       int base_row, int nrow) {
    int tid = threadIdx.x;
#pragma unroll
    for (int it = 0; it < (TM * (C / 4)) / NT; ++it) {
        int idx = tid + it * NT;
        int r = idx >> 5, c4 = idx & 31;
        float4 v = make_float4(0.f, 0.f, 0.f, 0.f);
        int gr = base_row + r;
        if (gr < nrow) v = ((const float4*)src)[gr * (C / 4) + c4];
        float* p = Ds + r * LDD + c4 * 4;
        p[0] = v.x; p[1] = v.y; p[2] = v.z; p[3] = v.w;
    }
}

__device__ __forceinline__ void gemm_128(const float* Ds, const float* Ws,
                                         int rt, int ct, unsigned long long acc[8][4]) {
    const float* dp = Ds + rt * 8 * LDD;
    const float* wp = Ws + ct * 2;
#pragma unroll
    for (int i = 0; i < 8; ++i)
#pragma unroll
        for (int j = 0; j < 4; ++j) acc[i][j] = 0ULL;
#pragma unroll 8
    for (int k = 0; k < C; ++k) {
        unsigned long long b[4];
#pragma unroll
        for (int j = 0; j < 4; ++j)
            b[j] = *(const unsigned long long*)(wp + k * C + j * 32);
#pragma unroll
        for (int i = 0; i < 8; ++i) {
            unsigned int au = __float_as_uint(dp[i * LDD + k]);
            unsigned long long a2;
            asm("mov.b64 %0, {%1, %1};" : "=l"(a2) : "r"(au));
#pragma unroll
            for (int j = 0; j < 4; ++j)
                asm("fma.rn.f32x2 %0, %1, %2, %3;"
                    : "=l"(acc[i][j]) : "l"(a2), "l"(b[j]), "l"(acc[i][j]));
        }
    }
}

__device__ __forceinline__ float2 unpack2(unsigned long long v) {
    unsigned int lo, hi;
    asm("mov.b64 {%0, %1}, %2;" : "=r"(lo), "=r"(hi) : "l"(v));
    return make_float2(__uint_as_float(lo), __uint_as_float(hi));
}

extern "C" __global__ void __launch_bounds__(NT, 1)
k_xf(const float* __restrict__ x, const float* __restrict__ Wi, int na) {
    float* smem = (float*)dynsmem;
    float* Ws = smem;
    float* Ds = smem + C * C;
    int tid = threadIdx.x, rt = tid >> 4, ct = tid & 15;
    int base = blockIdx.x * TM;

#pragma unroll
    for (int it = 0; it < (TM * (C / 4)) / NT; ++it) {
        int idx = tid + it * NT;
        int r = idx >> 5, c4 = idx & 31;
        int gr = base + r;
        if (gr < na) ((float4*)(g_agg + (size_t)gr * C))[c4] = make_float4(0.f, 0.f, 0.f, 0.f);
    }

    load_w(Ws, Wi);
    load_d(Ds, x, base, na);
    __syncthreads();

    unsigned long long acc[8][4];
    gemm_128(Ds, Ws, rt, ct, acc);

#pragma unroll
    for (int i = 0; i < 8; ++i) {
        int r = base + rt * 8 + i;
        if (r < na) {
#pragma unroll
            for (int j = 0; j < 4; ++j) {
                float2 v = unpack2(acc[i][j]);
                *(float2*)(&g_xf[r * C + ct * 2 + j * 32]) = v;
            }
        }
    }
}

extern "C" __global__ void __launch_bounds__(NT, 1)
k_out(const float* __restrict__ x,
      const float* __restrict__ Wo, const float* __restrict__ bo,
      const float* __restrict__ Wd, const float* __restrict__ bd,
      float* __restrict__ out_y, float* __restrict__ out_v, int na) {
    float* smem = (float*)dynsmem;
    float* Ws = smem;
    float* Ds = smem + C * C;
    float* Hs = Ds + TM * LDD;
    int tid = threadIdx.x, rt = tid >> 4, ct = tid & 15;
    int base = blockIdx.x * TM;

    float bov[8], bdv[8];
#pragma unroll
    for (int j = 0; j < 4; ++j) {
        int c0 = ct * 2 + j * 32;
        bov[2 * j] = bo[c0]; bov[2 * j + 1] = bo[c0 + 1];
        bdv[2 * j] = bd[c0]; bdv[2 * j + 1] = bd[c0 + 1];
    }

    load_w(Ws, Wo);
    load_d(Ds, g_agg, base, na);
    __syncthreads();

    unsigned long long acc[8][4];
    gemm_128(Ds, Ws, rt, ct, acc);

#pragma unroll
    for (int i = 0; i < 8; ++i) {
#pragma unroll
        for (int j = 0; j < 4; ++j) {
            float2 v = unpack2(acc[i][j]);
            v.x = ssp_f(v.x + bov[2 * j]);
            v.y = ssp_f(v.y + bov[2 * j + 1]);
            *(float2*)(&Hs[(rt * 8 + i) * LDD + ct * 2 + j * 32]) = v;
        }
    }
    __syncthreads();

    load_w(Ws, Wd);
    __syncthreads();

    gemm_128(Hs, Ws, rt, ct, acc);

#pragma unroll
    for (int i = 0; i < 8; ++i) {
        int r = base + rt * 8 + i;
        if (r < na) {
#pragma unroll
            for (int j = 0; j < 4; ++j) {
                int c0 = ct * 2 + j * 32;
                float2 v = unpack2(acc[i][j]);
                v.x += bdv[2 * j];
                v.y += bdv[2 * j + 1];
                float2 xv = *(const float2*)(&x[(size_t)r * C + c0]);
                *(float2*)(&out_v[(size_t)r * C + c0]) = v;
                *(float2*)(&out_y[(size_t)r * C + c0]) = make_float2(xv.x + v.x, xv.y + v.y);
            }
        }
    }
}

// ============================ launch ============================
extern "C" void kernel_launch(void* const* d_in, const int* in_sizes, int n_in,
                              void* d_out, int out_size) {
    const float* x    = (const float*)d_in[0];
    const float* dijk = (const float*)d_in[1];
    const int*   idxj = (const int*)d_in[2];
    const int*   segi = (const int*)d_in[3];
    const int*   segj = (const int*)d_in[4];
    const float* W1   = (const float*)d_in[5];
    const float* b1   = (const float*)d_in[6];
    const float* W2   = (const float*)d_in[7];
    const float* b2   = (const float*)d_in[8];
    const float* Wi   = (const float*)d_in[9];
    const float* Wo   = (const float*)d_in[10];
    const float* bo   = (const float*)d_in[11];
    const float* Wd   = (const float*)d_in[12];
    const float* bd   = (const float*)d_in[13];

    int na = in_sizes[0] / C;
    int ne = in_sizes[2];
    int ntiles = (ne + TM - 1) / TM;

    float* out_y = (float*)d_out;
    float* out_v = out_y + (size_t)na * C;

    const int SMEM_XF   = (C * C + TM * LDD) * 4;
    const int SMEM_OUT  = (C * C + 2 * TM * LDD) * 4;
    const int SMEM_EDGE = 3 * 128 * LDK * 4 + 2 * TM * 4;   // 209920

    cudaFuncSetAttribute(k_xf,        cudaFuncAttributeMaxDynamicSharedMemorySize, SMEM_XF);
    cudaFuncSetAttribute(k_out,       cudaFuncAttributeMaxDynamicSharedMemorySize, SMEM_OUT);
    cudaFuncSetAttribute(k_edges_mma, cudaFuncAttributeMaxDynamicSharedMemorySize, SMEM_EDGE);

    int g_atoms = (na + TM - 1) / TM;

    k_tr<<<dim3(4, 4), dim3(32, 8)>>>(W1, 0);
    k_tr<<<dim3(4, 4), dim3(32, 8)>>>(W2, 1);
    k_xf<<<g_atoms, NT, SMEM_XF>>>(x, Wi, na);
    k_edges_mma<<<148, NTE, SMEM_EDGE>>>(dijk, idxj, segi, segj, b1, b2, ne, ntiles);
    k_out<<<g_atoms, NT, SMEM_OUT>>>(x, Wo, bo, Wd, bd, out_y, out_v, na);
}

// round 8
// speedup vs baseline: 2.2931x; 1.1767x over previous
#include <cuda_runtime.h>
#include <cstdint>

#define C   128
#define LDK 136   // smem row stride (floats): 8-bank stride => conflict-free LDS.64
#define TME 64    // edge tile rows per group

extern __shared__ char dynsmem[];

// ---------------- scratch (device globals; allocation-free rule) ----------------
static __device__ __align__(16) float g_xf[20480 * C];
static __device__ __align__(16) float g_agg[20480 * C];
static __device__ __align__(16) float g_W1t[C * C];
static __device__ __align__(16) float g_W2t[C * C];
static __device__ __align__(16) float g_Wit[C * C];
static __device__ __align__(16) float g_Wot[C * C];
static __device__ __align__(16) float g_Wdt[C * C];

__device__ __forceinline__ float ssp_f(float x) {
    float t = __expf(-fabsf(x));
    return fmaxf(x, 0.0f) + __logf(1.0f + t) - 0.693147180559945f;
}

__device__ __forceinline__ float to_tf32(float x) {
    uint32_t u;
    asm("cvt.rna.tf32.f32 %0, %1;" : "=r"(u) : "f"(x));
    return __uint_as_float(u);
}

__device__ __forceinline__ void mma_tf32(float* d, const uint32_t* a, const uint32_t* b) {
    asm volatile(
        "mma.sync.aligned.m16n8k8.row.col.f32.tf32.tf32.f32 "
        "{%0,%1,%2,%3}, {%4,%5,%6,%7}, {%8,%9}, {%0,%1,%2,%3};"
        : "+f"(d[0]), "+f"(d[1]), "+f"(d[2]), "+f"(d[3])
        : "r"(a[0]), "r"(a[1]), "r"(a[2]), "r"(a[3]), "r"(b[0]), "r"(b[1]));
}

// Octet k-interleave: logical k j8 -> phys ((j8&3)<<1)|(j8>>2); pair {2c,2c+1} is one LDS.64.

// load a [128,128] weight tile (row-major, already transposed to [n][k]) into smem, tf32-rounded
__device__ __forceinline__ void load_w_tile(float* dst, const float* __restrict__ src,
                                            int tid, int nthr) {
    for (int idx = tid; idx < 128 * 32; idx += nthr) {
        int row = idx >> 5, c4 = idx & 31;
        float4 v = ((const float4*)src)[idx];
        float* d = dst + row * LDK + (c4 >> 1) * 8 + (c4 & 1);
        d[0] = to_tf32(v.x); d[2] = to_tf32(v.y); d[4] = to_tf32(v.z); d[6] = to_tf32(v.w);
    }
}

// load [rows,128] activation tile rows base.. into smem, tf32-rounded, zero-fill OOB
__device__ __forceinline__ void load_a_tile(float* dst, const float* __restrict__ src,
                                            int base, int nrow_total, int rows,
                                            int tid, int nthr) {
    for (int idx = tid; idx < rows * 32; idx += nthr) {
        int row = idx >> 5, c4 = idx & 31;
        float4 v = make_float4(0.f, 0.f, 0.f, 0.f);
        int gr = base + row;
        if (gr < nrow_total) v = ((const float4*)src)[gr * 32 + c4];
        float* d = dst + row * LDK + (c4 >> 1) * 8 + (c4 & 1);
        d[0] = to_tf32(v.x); d[2] = to_tf32(v.y); d[4] = to_tf32(v.z); d[6] = to_tf32(v.w);
    }
}

// one warp's 32x32 output tile over k=128: pa/pb pre-offset fragment pointers
__device__ __forceinline__ void gemm32x32(const float* pa, const float* pb, float acc[2][4][4]) {
#pragma unroll
    for (int mt = 0; mt < 2; ++mt)
#pragma unroll
        for (int nt = 0; nt < 4; ++nt)
#pragma unroll
            for (int q = 0; q < 4; ++q) acc[mt][nt][q] = 0.f;
#pragma unroll
    for (int kk = 0; kk < 16; ++kk) {
        const int kb = kk * 8;
        uint32_t af[2][4], bf[4][2];
#pragma unroll
        for (int mt = 0; mt < 2; ++mt) {
            float2 xv = *(const float2*)(pa + mt * 16 * LDK + kb);
            float2 yv = *(const float2*)(pa + (mt * 16 + 8) * LDK + kb);
            af[mt][0] = __float_as_uint(xv.x); af[mt][2] = __float_as_uint(xv.y);
            af[mt][1] = __float_as_uint(yv.x); af[mt][3] = __float_as_uint(yv.y);
        }
#pragma unroll
        for (int nt = 0; nt < 4; ++nt) {
            float2 zv = *(const float2*)(pb + nt * 8 * LDK + kb);
            bf[nt][0] = __float_as_uint(zv.x); bf[nt][1] = __float_as_uint(zv.y);
        }
#pragma unroll
        for (int mt = 0; mt < 2; ++mt)
#pragma unroll
            for (int nt = 0; nt < 4; ++nt)
                mma_tf32(acc[mt][nt], af[mt], bf[nt]);
    }
}

#define BARG() asm volatile("bar.sync %0, 256;" :: "r"(grp + 1) : "memory")

// =====================================================================
// Edge kernel: 2 independent 8-warp groups, each pipelining TM=64 tiles.
// agg += scatter( ssp(ssp(dijk@W1+b1)@W2+b2) * xf[idx_j] )
// =====================================================================
extern "C" __global__ void __launch_bounds__(512, 1)
k_edges_mma(const float* __restrict__ dijk,
            const int* __restrict__ idx_j,
            const int* __restrict__ seg_i,
            const int* __restrict__ seg_j,
            const float* __restrict__ b1, const float* __restrict__ b2,
            int ne, int nt64) {
    float* sA0 = (float*)dynsmem;                 // 64 x LDK (group 0)
    float* sA1 = sA0 + TME * LDK;                 // 64 x LDK (group 1)
    float* sB1 = sA1 + TME * LDK;                 // W1t 128 x LDK
    float* sB2 = sB1 + 128 * LDK;                 // W2t 128 x LDK
    int*   sg  = (int*)(sB2 + 128 * LDK);         // [2][128] gather

    const int tid = threadIdx.x;
    const int grp = tid >> 8, gt = tid & 255;
    const int wid = gt >> 5, lane = tid & 31;
    const int g = lane >> 2, c = lane & 3;
    const int mr = (wid & 1) * 32;                // warp row-block within 64-row tile
    const int nc = (wid >> 1) * 32;               // warp col-block
    const int pe = ((c & 1) << 2) + (c >> 1);     // phys pos of logical col 2c within octet
    const int po = pe + 2;

    float* sA  = grp ? sA1 : sA0;
    int* s_aj = sg + grp * 128;
    int* s_ti = s_aj + TME;

    float be1[4], bo1[4], be2[4], bo2[4];
#pragma unroll
    for (int nt = 0; nt < 4; ++nt) {
        int col = nc + nt * 8 + 2 * c;
        be1[nt] = b1[col]; bo1[nt] = b1[col + 1];
        be2[nt] = b2[col]; bo2[nt] = b2[col + 1];
    }

    load_w_tile(sB1, g_W1t, tid, 512);
    load_w_tile(sB2, g_W2t, tid, 512);
    __syncthreads();

    const float* pa  = sA  + (mr + g) * LDK + 2 * c;
    const float* pb1 = sB1 + (nc + g) * LDK + 2 * c;
    const float* pb2 = sB2 + (nc + g) * LDK + 2 * c;

    for (int t = blockIdx.x * 2 + grp; t < nt64; t += gridDim.x * 2) {
        const int base = t * TME;

        if (gt < TME) {
            int e = base + gt, aj = 0, ti = -1;
            if (e < ne) { int p = seg_j[e]; aj = idx_j[p]; ti = seg_i[p]; }
            s_aj[gt] = aj; s_ti[gt] = ti;
        }
        load_a_tile(sA, dijk, base, ne, TME, gt, 256);
        BARG();

        float acc[2][4][4];
        gemm32x32(pa, pb1, acc);
        BARG();

        // epi1: H = tf32(ssp(D + b1)) -> sA
#pragma unroll
        for (int mt = 0; mt < 2; ++mt) {
            int row = mr + mt * 16 + g;
#pragma unroll
            for (int nt = 0; nt < 4; ++nt) {
                float* d0 = sA + row * LDK + nc + nt * 8;
                float* d1 = d0 + 8 * LDK;
                d0[pe] = to_tf32(ssp_f(acc[mt][nt][0] + be1[nt]));
                d0[po] = to_tf32(ssp_f(acc[mt][nt][1] + bo1[nt]));
                d1[pe] = to_tf32(ssp_f(acc[mt][nt][2] + be1[nt]));
                d1[po] = to_tf32(ssp_f(acc[mt][nt][3] + bo1[nt]));
            }
        }
        BARG();

        gemm32x32(pa, pb2, acc);
        BARG();

        // epi2a: W = ssp(D + b2) -> sA (fp32)
#pragma unroll
        for (int mt = 0; mt < 2; ++mt) {
            int row = mr + mt * 16 + g;
#pragma unroll
            for (int nt = 0; nt < 4; ++nt) {
                float* d0 = sA + row * LDK + nc + nt * 8;
                float* d1 = d0 + 8 * LDK;
                d0[pe] = ssp_f(acc[mt][nt][0] + be2[nt]);
                d0[po] = ssp_f(acc[mt][nt][1] + bo2[nt]);
                d1[pe] = ssp_f(acc[mt][nt][2] + be2[nt]);
                d1[po] = ssp_f(acc[mt][nt][3] + bo2[nt]);
            }
        }
        BARG();

        // epi2b: msg = W * xf[aj]; run-length reduce over sorted targets
        {
            const int col = gt & 127;
            const int pc = (col & ~7) + ((col & 3) << 1) + ((col >> 2) & 1);
            const int r0 = (gt >> 7) * 32;
            float acc1 = 0.f;
            int cur = -1;
#pragma unroll 4
            for (int rr = 0; rr < 32; ++rr) {
                int row = r0 + rr;
                int tgt = s_ti[row];
                float wv = sA[row * LDK + pc];
                float xv = __ldg(&g_xf[(size_t)s_aj[row] * C + col]);
                if (tgt != cur) {
                    if (cur >= 0) atomicAdd(&g_agg[(size_t)cur * C + col], acc1);
                    acc1 = 0.f; cur = tgt;
                }
                acc1 = fmaf(wv, xv, acc1);
            }
            if (cur >= 0) atomicAdd(&g_agg[(size_t)cur * C + col], acc1);
        }
        BARG();
    }
}

// =====================================================================
// k_xf: xf = x @ Wi (tf32 mma), also zeroes g_agg rows of this tile
// =====================================================================
extern "C" __global__ void __launch_bounds__(512, 1)
k_xf_mma(const float* __restrict__ x, int na) {
    float* sA = (float*)dynsmem;        // 128 x LDK
    float* sB = sA + 128 * LDK;         // Wit
    const int tid = threadIdx.x, wid = tid >> 5, lane = tid & 31;
    const int g = lane >> 2, c = lane & 3;
    const int mr = (wid & 3) * 32, nc = (wid >> 2) * 32;
    const int base = blockIdx.x * 128;

    for (int idx = tid; idx < 128 * 32; idx += 512) {
        int row = idx >> 5, c4 = idx & 31;
        int gr = base + row;
        if (gr < na) ((float4*)(g_agg + (size_t)gr * C))[c4] = make_float4(0.f, 0.f, 0.f, 0.f);
    }
    load_w_tile(sB, g_Wit, tid, 512);
    load_a_tile(sA, x, base, na, 128, tid, 512);
    __syncthreads();

    float acc[2][4][4];
    gemm32x32(sA + (mr + g) * LDK + 2 * c, sB + (nc + g) * LDK + 2 * c, acc);

#pragma unroll
    for (int mt = 0; mt < 2; ++mt)
#pragma unroll
        for (int half = 0; half < 2; ++half) {
            int r = base + mr + mt * 16 + half * 8 + g;
            if (r < na) {
#pragma unroll
                for (int nt = 0; nt < 4; ++nt) {
                    int col = nc + nt * 8 + 2 * c;
                    float2 v = make_float2(acc[mt][nt][half * 2], acc[mt][nt][half * 2 + 1]);
                    *(float2*)(&g_xf[(size_t)r * C + col]) = v;
                }
            }
        }
}

// =====================================================================
// k_out: h = ssp(agg@Wo+bo); v = h@Wd+bd; y = x+v; writes (y, v)
// =====================================================================
extern "C" __global__ void __launch_bounds__(512, 1)
k_out_mma(const float* __restrict__ x,
          const float* __restrict__ bo, const float* __restrict__ bd,
          float* __restrict__ out_y, float* __restrict__ out_v, int na) {
    float* sA  = (float*)dynsmem;       // 128 x LDK
    float* sBo = sA + 128 * LDK;        // Wot
    float* sBd = sBo + 128 * LDK;       // Wdt
    const int tid = threadIdx.x, wid = tid >> 5, lane = tid & 31;
    const int g = lane >> 2, c = lane & 3;
    const int mr = (wid & 3) * 32, nc = (wid >> 2) * 32;
    const int pe = ((c & 1) << 2) + (c >> 1);
    const int po = pe + 2;
    const int base = blockIdx.x * 128;

    float boe[4], boo[4], bde[4], bdo[4];
#pragma unroll
    for (int nt = 0; nt < 4; ++nt) {
        int col = nc + nt * 8 + 2 * c;
        boe[nt] = bo[col]; boo[nt] = bo[col + 1];
        bde[nt] = bd[col]; bdo[nt] = bd[col + 1];
    }

    load_w_tile(sBo, g_Wot, tid, 512);
    load_w_tile(sBd, g_Wdt, tid, 512);
    load_a_tile(sA, g_agg, base, na, 128, tid, 512);
    __syncthreads();

    const float* pa = sA + (mr + g) * LDK + 2 * c;
    float acc[2][4][4];
    gemm32x32(pa, sBo + (nc + g) * LDK + 2 * c, acc);
    __syncthreads();   // all warps done reading sA

    // epi1: H = tf32(ssp(D + bo)) -> sA
#pragma unroll
    for (int mt = 0; mt < 2; ++mt) {
        int row = mr + mt * 16 + g;
#pragma unroll
        for (int nt = 0; nt < 4; ++nt) {
            float* d0 = sA + row * LDK + nc + nt * 8;
            float* d1 = d0 + 8 * LDK;
            d0[pe] = to_tf32(ssp_f(acc[mt][nt][0] + boe[nt]));
            d0[po] = to_tf32(ssp_f(acc[mt][nt][1] + boo[nt]));
            d1[pe] = to_tf32(ssp_f(acc[mt][nt][2] + boe[nt]));
            d1[po] = to_tf32(ssp_f(acc[mt][nt][3] + boo[nt]));
        }
    }
    __syncthreads();

    gemm32x32(pa, sBd + (nc + g) * LDK + 2 * c, acc);

    // final epilogue: v = D + bd; y = x + v
#pragma unroll
    for (int mt = 0; mt < 2; ++mt)
#pragma unroll
        for (int half = 0; half < 2; ++half) {
            int r = base + mr + mt * 16 + half * 8 + g;
            if (r < na) {
#pragma unroll
                for (int nt = 0; nt < 4; ++nt) {
                    int col = nc + nt * 8 + 2 * c;
                    float vx = acc[mt][nt][half * 2]     + bde[nt];
                    float vy = acc[mt][nt][half * 2 + 1] + bdo[nt];
                    float2 xv = *(const float2*)(&x[(size_t)r * C + col]);
                    *(float2*)(&out_v[(size_t)r * C + col]) = make_float2(vx, vy);
                    *(float2*)(&out_y[(size_t)r * C + col]) = make_float2(xv.x + vx, xv.y + vy);
                }
            }
        }
}

// ---------------- transpose 5 weights W[k][n] -> Wt[n][k] ----------------
extern "C" __global__ void k_tr5(const float* __restrict__ s0, const float* __restrict__ s1,
                                 const float* __restrict__ s2, const float* __restrict__ s3,
                                 const float* __restrict__ s4) {
    __shared__ float t[32][33];
    const float* s; float* d;
    switch (blockIdx.z) {
        case 0: s = s0; d = g_W1t; break;
        case 1: s = s1; d = g_W2t; break;
        case 2: s = s2; d = g_Wit; break;
        case 3: s = s3; d = g_Wot; break;
        default: s = s4; d = g_Wdt; break;
    }
    int bx = blockIdx.x, by = blockIdx.y;
    int xx = threadIdx.x, yy = threadIdx.y;
#pragma unroll
    for (int i = 0; i < 32; i += 8) t[yy + i][xx] = s[(by * 32 + yy + i) * C + bx * 32 + xx];
    __syncthreads();
#pragma unroll
    for (int i = 0; i < 32; i += 8) d[(bx * 32 + yy + i) * C + by * 32 + xx] = t[xx][yy + i];
}

// ============================ launch ============================
extern "C" void kernel_launch(void* const* d_in, const int* in_sizes, int n_in,
                              void* d_out, int out_size) {
    const float* x    = (const float*)d_in[0];
    const float* dijk = (const float*)d_in[1];
    const int*   idxj = (const int*)d_in[2];
    const int*   segi = (const int*)d_in[3];
    const int*   segj = (const int*)d_in[4];
    const float* W1   = (const float*)d_in[5];
    const float* b1   = (const float*)d_in[6];
    const float* W2   = (const float*)d_in[7];
    const float* b2   = (const float*)d_in[8];
    const float* Wi   = (const float*)d_in[9];
    const float* Wo   = (const float*)d_in[10];
    const float* bo   = (const float*)d_in[11];
    const float* Wd   = (const float*)d_in[12];
    const float* bd   = (const float*)d_in[13];

    int na = in_sizes[0] / C;
    int ne = in_sizes[2];
    int nt64 = (ne + TME - 1) / TME;
    int g_atoms = (na + 127) / 128;

    float* out_y = (float*)d_out;
    float* out_v = out_y + (size_t)na * C;

    const int SM_XF   = 2 * 128 * LDK * 4;                       // 139264
    const int SM_OUT  = 3 * 128 * LDK * 4;                       // 208896
    const int SM_EDGE = (2 * TME + 2 * 128) * LDK * 4 + 1024;    // 209920

    cudaFuncSetAttribute(k_xf_mma,    cudaFuncAttributeMaxDynamicSharedMemorySize, SM_XF);
    cudaFuncSetAttribute(k_out_mma,   cudaFuncAttributeMaxDynamicSharedMemorySize, SM_OUT);
    cudaFuncSetAttribute(k_edges_mma, cudaFuncAttributeMaxDynamicSharedMemorySize, SM_EDGE);

    k_tr5<<<dim3(4, 4, 5), dim3(32, 8)>>>(W1, W2, Wi, Wo, Wd);
    k_xf_mma<<<g_atoms, 512, SM_XF>>>(x, na);
    k_edges_mma<<<148, 512, SM_EDGE>>>(dijk, idxj, segi, segj, b1, b2, ne, nt64);
    k_out_mma<<<g_atoms, 512, SM_OUT>>>(x, bo, bd, out_y, out_v, na);
}

// round 9
// speedup vs baseline: 2.4934x; 1.0874x over previous
#include <cuda_runtime.h>
#include <cstdint>

#define C   128
#define LDK 136   // smem row stride (floats): 8-bank stride => conflict-free LDS.64
#define TME 64    // edge tile rows per group

extern __shared__ char dynsmem[];

// ---------------- scratch (device globals; allocation-free rule) ----------------
static __device__ __align__(16) float g_xf[20480 * C];
static __device__ __align__(16) float g_agg[20480 * C];
static __device__ __align__(16) float g_W1t[C * C];
static __device__ __align__(16) float g_W2t[C * C];
static __device__ __align__(16) float g_Wit[C * C];
static __device__ __align__(16) float g_Wot[C * C];
static __device__ __align__(16) float g_Wdt[C * C];

__device__ __forceinline__ float ssp_f(float x) {
    float t = __expf(-fabsf(x));
    return fmaxf(x, 0.0f) + __logf(1.0f + t) - 0.693147180559945f;
}

__device__ __forceinline__ float to_tf32(float x) {
    uint32_t u;
    asm("cvt.rna.tf32.f32 %0, %1;" : "=r"(u) : "f"(x));
    return __uint_as_float(u);
}

__device__ __forceinline__ void mma_tf32(float* d, const uint32_t* a, const uint32_t* b) {
    asm volatile(
        "mma.sync.aligned.m16n8k8.row.col.f32.tf32.tf32.f32 "
        "{%0,%1,%2,%3}, {%4,%5,%6,%7}, {%8,%9}, {%0,%1,%2,%3};"
        : "+f"(d[0]), "+f"(d[1]), "+f"(d[2]), "+f"(d[3])
        : "r"(a[0]), "r"(a[1]), "r"(a[2]), "r"(a[3]), "r"(b[0]), "r"(b[1]));
}

// Octet k-interleave: logical k j8 -> phys ((j8&3)<<1)|(j8>>2); pair {2c,2c+1} is one LDS.64.

__device__ __forceinline__ void load_w_tile(float* dst, const float* __restrict__ src,
                                            int tid, int nthr) {
    for (int idx = tid; idx < 128 * 32; idx += nthr) {
        int row = idx >> 5, c4 = idx & 31;
        float4 v = ((const float4*)src)[idx];
        float* d = dst + row * LDK + (c4 >> 1) * 8 + (c4 & 1);
        d[0] = to_tf32(v.x); d[2] = to_tf32(v.y); d[4] = to_tf32(v.z); d[6] = to_tf32(v.w);
    }
}

__device__ __forceinline__ void load_a_tile(float* dst, const float* __restrict__ src,
                                            int base, int nrow_total, int rows,
                                            int tid, int nthr) {
    for (int idx = tid; idx < rows * 32; idx += nthr) {
        int row = idx >> 5, c4 = idx & 31;
        float4 v = make_float4(0.f, 0.f, 0.f, 0.f);
        int gr = base + row;
        if (gr < nrow_total) v = ((const float4*)src)[gr * 32 + c4];
        float* d = dst + row * LDK + (c4 >> 1) * 8 + (c4 & 1);
        d[0] = to_tf32(v.x); d[2] = to_tf32(v.y); d[4] = to_tf32(v.z); d[6] = to_tf32(v.w);
    }
}

// one warp's 32x32 output tile over k=128
__device__ __forceinline__ void gemm32x32(const float* pa, const float* pb, float acc[2][4][4]) {
#pragma unroll
    for (int mt = 0; mt < 2; ++mt)
#pragma unroll
        for (int nt = 0; nt < 4; ++nt)
#pragma unroll
            for (int q = 0; q < 4; ++q) acc[mt][nt][q] = 0.f;
#pragma unroll
    for (int kk = 0; kk < 16; ++kk) {
        const int kb = kk * 8;
        uint32_t af[2][4], bf[4][2];
#pragma unroll
        for (int mt = 0; mt < 2; ++mt) {
            float2 xv = *(const float2*)(pa + mt * 16 * LDK + kb);
            float2 yv = *(const float2*)(pa + (mt * 16 + 8) * LDK + kb);
            af[mt][0] = __float_as_uint(xv.x); af[mt][2] = __float_as_uint(xv.y);
            af[mt][1] = __float_as_uint(yv.x); af[mt][3] = __float_as_uint(yv.y);
        }
#pragma unroll
        for (int nt = 0; nt < 4; ++nt) {
            float2 zv = *(const float2*)(pb + nt * 8 * LDK + kb);
            bf[nt][0] = __float_as_uint(zv.x); bf[nt][1] = __float_as_uint(zv.y);
        }
#pragma unroll
        for (int mt = 0; mt < 2; ++mt)
#pragma unroll
            for (int nt = 0; nt < 4; ++nt)
                mma_tf32(acc[mt][nt], af[mt], bf[nt]);
    }
}

#define BARG() asm volatile("bar.sync %0, 256;" :: "r"(grp + 1) : "memory")

// =====================================================================
// Edge kernel: 2 independent 8-warp groups; register-prefetched A tiles.
// agg += scatter( ssp(ssp(dijk@W1+b1)@W2+b2) * xf[idx_j] )
// =====================================================================
extern "C" __global__ void __launch_bounds__(512, 1)
k_edges_mma(const float* __restrict__ dijk,
            const int* __restrict__ idx_j,
            const int* __restrict__ seg_i,
            const int* __restrict__ seg_j,
            const float* __restrict__ b1, const float* __restrict__ b2,
            int ne, int nt64) {
    float* sA0 = (float*)dynsmem;                 // 64 x LDK (group 0)
    float* sA1 = sA0 + TME * LDK;                 // 64 x LDK (group 1)
    float* sB1 = sA1 + TME * LDK;                 // W1t 128 x LDK
    float* sB2 = sB1 + 128 * LDK;                 // W2t 128 x LDK
    int*   sg  = (int*)(sB2 + 128 * LDK);         // [2][128] gather
    float* sb1 = (float*)(sg + 256);              // bias1 [128]
    float* sb2 = sb1 + 128;                       // bias2 [128]

    const int tid = threadIdx.x;
    const int grp = tid >> 8, gt = tid & 255;
    const int wid = gt >> 5, lane = tid & 31;
    const int g = lane >> 2, c = lane & 3;
    const int mr = (wid & 1) * 32;                // warp row-block within 64-row tile
    const int nc = (wid >> 1) * 32;               // warp col-block
    const int pe = ((c & 1) << 2) + (c >> 1);     // phys pos of logical col 2c within octet
    const int po = pe + 2;

    float* sA  = grp ? sA1 : sA0;
    int* s_aj = sg + grp * 128;
    int* s_ti = s_aj + TME;

    if (tid < 128) sb1[tid] = b1[tid];
    else if (tid < 256) sb2[tid - 128] = b2[tid - 128];

    load_w_tile(sB1, g_W1t, tid, 512);
    load_w_tile(sB2, g_W2t, tid, 512);
    __syncthreads();

    const float* pa  = sA  + (mr + g) * LDK + 2 * c;
    const float* pb1 = sB1 + (nc + g) * LDK + 2 * c;
    const float* pb2 = sB2 + (nc + g) * LDK + 2 * c;

    const int tstride = gridDim.x * 2;
    int t = blockIdx.x * 2 + grp;

    // per-thread A-row mapping for the 8 prefetch quads
    const int prow = gt >> 5;        // base row (advances by 8 per quad)
    const int pc4  = gt & 31;

    // ---- prologue prefetch for first tile ----
    float4 pf[8];
    int pf_aj = 0, pf_ti = -1;
    {
        int base = t * TME;
#pragma unroll
        for (int i = 0; i < 8; ++i) {
            int gr = base + prow + i * 8;
            pf[i] = (t < nt64 && gr < ne) ? ((const float4*)dijk)[gr * 32 + pc4]
                                          : make_float4(0.f, 0.f, 0.f, 0.f);
        }
        if (gt < TME) {
            int e = base + gt;
            if (t < nt64 && e < ne) { int p = seg_j[e]; pf_aj = idx_j[p]; pf_ti = seg_i[p]; }
        }
    }

    for (; t < nt64; ) {
        // ---- commit prefetched tile to smem ----
#pragma unroll
        for (int i = 0; i < 8; ++i) {
            int row = prow + i * 8;
            float* d = sA + row * LDK + (pc4 >> 1) * 8 + (pc4 & 1);
            d[0] = to_tf32(pf[i].x); d[2] = to_tf32(pf[i].y);
            d[4] = to_tf32(pf[i].z); d[6] = to_tf32(pf[i].w);
        }
        if (gt < TME) { s_aj[gt] = pf_aj; s_ti[gt] = pf_ti; }
        BARG();

        // ---- issue prefetch for next tile (drains behind the GEMMs) ----
        const int tn = t + tstride;
        {
            int base = tn * TME;
#pragma unroll
            for (int i = 0; i < 8; ++i) {
                int gr = base + prow + i * 8;
                pf[i] = (tn < nt64 && gr < ne) ? ((const float4*)dijk)[gr * 32 + pc4]
                                               : make_float4(0.f, 0.f, 0.f, 0.f);
            }
            pf_aj = 0; pf_ti = -1;
            if (gt < TME) {
                int e = base + gt;
                if (tn < nt64 && e < ne) { int p = seg_j[e]; pf_aj = idx_j[p]; pf_ti = seg_i[p]; }
            }
        }

        float acc[2][4][4];
        gemm32x32(pa, pb1, acc);
        BARG();

        // epi1: H = tf32(ssp(D + b1)) -> sA
#pragma unroll
        for (int mt = 0; mt < 2; ++mt) {
            int row = mr + mt * 16 + g;
#pragma unroll
            for (int nt = 0; nt < 4; ++nt) {
                int col = nc + nt * 8 + 2 * c;
                float2 bb = *(const float2*)(sb1 + col);
                float* d0 = sA + row * LDK + nc + nt * 8;
                float* d1 = d0 + 8 * LDK;
                d0[pe] = to_tf32(ssp_f(acc[mt][nt][0] + bb.x));
                d0[po] = to_tf32(ssp_f(acc[mt][nt][1] + bb.y));
                d1[pe] = to_tf32(ssp_f(acc[mt][nt][2] + bb.x));
                d1[po] = to_tf32(ssp_f(acc[mt][nt][3] + bb.y));
            }
        }
        BARG();

        gemm32x32(pa, pb2, acc);
        BARG();

        // epi2a: W = ssp(D + b2) -> sA (fp32)
#pragma unroll
        for (int mt = 0; mt < 2; ++mt) {
            int row = mr + mt * 16 + g;
#pragma unroll
            for (int nt = 0; nt < 4; ++nt) {
                int col = nc + nt * 8 + 2 * c;
                float2 bb = *(const float2*)(sb2 + col);
                float* d0 = sA + row * LDK + nc + nt * 8;
                float* d1 = d0 + 8 * LDK;
                d0[pe] = ssp_f(acc[mt][nt][0] + bb.x);
                d0[po] = ssp_f(acc[mt][nt][1] + bb.y);
                d1[pe] = ssp_f(acc[mt][nt][2] + bb.x);
                d1[po] = ssp_f(acc[mt][nt][3] + bb.y);
            }
        }
        BARG();

        // epi2b: msg = W * xf[aj]; run-length reduce over sorted targets
        {
            const int col = gt & 127;
            const int pc = (col & ~7) + ((col & 3) << 1) + ((col >> 2) & 1);
            const int r0 = (gt >> 7) * 32;
            float acc1 = 0.f;
            int cur = -1;
#pragma unroll
            for (int rr = 0; rr < 32; ++rr) {
                int row = r0 + rr;
                int tgt = s_ti[row];
                float wv = sA[row * LDK + pc];
                float xv = __ldg(&g_xf[(size_t)s_aj[row] * C + col]);
                if (tgt != cur) {
                    if (cur >= 0) atomicAdd(&g_agg[(size_t)cur * C + col], acc1);
                    acc1 = 0.f; cur = tgt;
                }
                acc1 = fmaf(wv, xv, acc1);
            }
            if (cur >= 0) atomicAdd(&g_agg[(size_t)cur * C + col], acc1);
        }
        BARG();
        t = tn;
    }
}

// =====================================================================
// k_xf: xf = x @ Wi (tf32 mma), also zeroes g_agg rows of this tile
// =====================================================================
extern "C" __global__ void __launch_bounds__(512, 1)
k_xf_mma(const float* __restrict__ x, int na) {
    float* sA = (float*)dynsmem;        // 128 x LDK
    float* sB = sA + 128 * LDK;         // Wit
    const int tid = threadIdx.x, wid = tid >> 5, lane = tid & 31;
    const int g = lane >> 2, c = lane & 3;
    const int mr = (wid & 3) * 32, nc = (wid >> 2) * 32;
    const int base = blockIdx.x * 128;

    for (int idx = tid; idx < 128 * 32; idx += 512) {
        int row = idx >> 5, c4 = idx & 31;
        int gr = base + row;
        if (gr < na) ((float4*)(g_agg + (size_t)gr * C))[c4] = make_float4(0.f, 0.f, 0.f, 0.f);
    }
    load_w_tile(sB, g_Wit, tid, 512);
    load_a_tile(sA, x, base, na, 128, tid, 512);
    __syncthreads();

    float acc[2][4][4];
    gemm32x32(sA + (mr + g) * LDK + 2 * c, sB + (nc + g) * LDK + 2 * c, acc);

#pragma unroll
    for (int mt = 0; mt < 2; ++mt)
#pragma unroll
        for (int half = 0; half < 2; ++half) {
            int r = base + mr + mt * 16 + half * 8 + g;
            if (r < na) {
#pragma unroll
                for (int nt = 0; nt < 4; ++nt) {
                    int col = nc + nt * 8 + 2 * c;
                    float2 v = make_float2(acc[mt][nt][half * 2], acc[mt][nt][half * 2 + 1]);
                    *(float2*)(&g_xf[(size_t)r * C + col]) = v;
                }
            }
        }
}

// =====================================================================
// k_out: h = ssp(agg@Wo+bo); v = h@Wd+bd; y = x+v; writes (y, v)
// =====================================================================
extern "C" __global__ void __launch_bounds__(512, 1)
k_out_mma(const float* __restrict__ x,
          const float* __restrict__ bo, const float* __restrict__ bd,
          float* __restrict__ out_y, float* __restrict__ out_v, int na) {
    float* sA  = (float*)dynsmem;       // 128 x LDK
    float* sBo = sA + 128 * LDK;        // Wot
    float* sBd = sBo + 128 * LDK;       // Wdt
    const int tid = threadIdx.x, wid = tid >> 5, lane = tid & 31;
    const int g = lane >> 2, c = lane & 3;
    const int mr = (wid & 3) * 32, nc = (wid >> 2) * 32;
    const int pe = ((c & 1) << 2) + (c >> 1);
    const int po = pe + 2;
    const int base = blockIdx.x * 128;

    float boe[4], boo[4], bde[4], bdo[4];
#pragma unroll
    for (int nt = 0; nt < 4; ++nt) {
        int col = nc + nt * 8 + 2 * c;
        boe[nt] = bo[col]; boo[nt] = bo[col + 1];
        bde[nt] = bd[col]; bdo[nt] = bd[col + 1];
    }

    load_w_tile(sBo, g_Wot, tid, 512);
    load_w_tile(sBd, g_Wdt, tid, 512);
    load_a_tile(sA, g_agg, base, na, 128, tid, 512);
    __syncthreads();

    const float* pa = sA + (mr + g) * LDK + 2 * c;
    float acc[2][4][4];
    gemm32x32(pa, sBo + (nc + g) * LDK + 2 * c, acc);
    __syncthreads();   // all warps done reading sA

    // epi1: H = tf32(ssp(D + bo)) -> sA
#pragma unroll
    for (int mt = 0; mt < 2; ++mt) {
        int row = mr + mt * 16 + g;
#pragma unroll
        for (int nt = 0; nt < 4; ++nt) {
            float* d0 = sA + row * LDK + nc + nt * 8;
            float* d1 = d0 + 8 * LDK;
            d0[pe] = to_tf32(ssp_f(acc[mt][nt][0] + boe[nt]));
            d0[po] = to_tf32(ssp_f(acc[mt][nt][1] + boo[nt]));
            d1[pe] = to_tf32(ssp_f(acc[mt][nt][2] + boe[nt]));
            d1[po] = to_tf32(ssp_f(acc[mt][nt][3] + boo[nt]));
        }
    }
    __syncthreads();

    gemm32x32(pa, sBd + (nc + g) * LDK + 2 * c, acc);

    // final epilogue: v = D + bd; y = x + v
#pragma unroll
    for (int mt = 0; mt < 2; ++mt)
#pragma unroll
        for (int half = 0; half < 2; ++half) {
            int r = base + mr + mt * 16 + half * 8 + g;
            if (r < na) {
#pragma unroll
                for (int nt = 0; nt < 4; ++nt) {
                    int col = nc + nt * 8 + 2 * c;
                    float vx = acc[mt][nt][half * 2]     + bde[nt];
                    float vy = acc[mt][nt][half * 2 + 1] + bdo[nt];
                    float2 xv = *(const float2*)(&x[(size_t)r * C + col]);
                    *(float2*)(&out_v[(size_t)r * C + col]) = make_float2(vx, vy);
                    *(float2*)(&out_y[(size_t)r * C + col]) = make_float2(xv.x + vx, xv.y + vy);
                }
            }
        }
}

// ---------------- transpose 5 weights W[k][n] -> Wt[n][k] ----------------
extern "C" __global__ void k_tr5(const float* __restrict__ s0, const float* __restrict__ s1,
                                 const float* __restrict__ s2, const float* __restrict__ s3,
                                 const float* __restrict__ s4) {
    __shared__ float t[32][33];
    const float* s; float* d;
    switch (blockIdx.z) {
        case 0: s = s0; d = g_W1t; break;
        case 1: s = s1; d = g_W2t; break;
        case 2: s = s2; d = g_Wit; break;
        case 3: s = s3; d = g_Wot; break;
        default: s = s4; d = g_Wdt; break;
    }
    int bx = blockIdx.x, by = blockIdx.y;
    int xx = threadIdx.x, yy = threadIdx.y;
#pragma unroll
    for (int i = 0; i < 32; i += 8) t[yy + i][xx] = s[(by * 32 + yy + i) * C + bx * 32 + xx];
    __syncthreads();
#pragma unroll
    for (int i = 0; i < 32; i += 8) d[(bx * 32 + yy + i) * C + by * 32 + xx] = t[xx][yy + i];
}

// ============================ launch ============================
extern "C" void kernel_launch(void* const* d_in, const int* in_sizes, int n_in,
                              void* d_out, int out_size) {
    const float* x    = (const float*)d_in[0];
    const float* dijk = (const float*)d_in[1];
    const int*   idxj = (const int*)d_in[2];
    const int*   segi = (const int*)d_in[3];
    const int*   segj = (const int*)d_in[4];
    const float* W1   = (const float*)d_in[5];
    const float* b1   = (const float*)d_in[6];
    const float* W2   = (const float*)d_in[7];
    const float* b2   = (const float*)d_in[8];
    const float* Wi   = (const float*)d_in[9];
    const float* Wo   = (const float*)d_in[10];
    const float* bo   = (const float*)d_in[11];
    const float* Wd   = (const float*)d_in[12];
    const float* bd   = (const float*)d_in[13];

    int na = in_sizes[0] / C;
    int ne = in_sizes[2];
    int nt64 = (ne + TME - 1) / TME;
    int g_atoms = (na + 127) / 128;

    float* out_y = (float*)d_out;
    float* out_v = out_y + (size_t)na * C;

    const int SM_XF   = 2 * 128 * LDK * 4;                        // 139264
    const int SM_OUT  = 3 * 128 * LDK * 4;                        // 208896
    const int SM_EDGE = (2 * TME + 2 * 128) * LDK * 4 + 2048;     // 210944

    cudaFuncSetAttribute(k_xf_mma,    cudaFuncAttributeMaxDynamicSharedMemorySize, SM_XF);
    cudaFuncSetAttribute(k_out_mma,   cudaFuncAttributeMaxDynamicSharedMemorySize, SM_OUT);
    cudaFuncSetAttribute(k_edges_mma, cudaFuncAttributeMaxDynamicSharedMemorySize, SM_EDGE);

    k_tr5<<<dim3(4, 4, 5), dim3(32, 8)>>>(W1, W2, Wi, Wo, Wd);
    k_xf_mma<<<g_atoms, 512, SM_XF>>>(x, na);
    k_edges_mma<<<148, 512, SM_EDGE>>>(dijk, idxj, segi, segj, b1, b2, ne, nt64);
    k_out_mma<<<g_atoms, 512, SM_OUT>>>(x, bo, bd, out_y, out_v, na);
}

// round 10
// speedup vs baseline: 2.7893x; 1.1187x over previous
#include <cuda_runtime.h>
#include <cstdint>

#define C   128
#define LDK 136   // smem row stride (floats): 8-bank stride => conflict-free LDS.64
#define TME 32    // edge tile rows per group
#define NG  4     // independent warp-groups per CTA

extern __shared__ char dynsmem[];

// ---------------- scratch (device globals; allocation-free rule) ----------------
static __device__ __align__(16) float g_xf[20480 * C];
static __device__ __align__(16) float g_agg[20480 * C];
static __device__ __align__(16) float g_W1t[C * C];
static __device__ __align__(16) float g_W2t[C * C];
static __device__ __align__(16) float g_Wit[C * C];
static __device__ __align__(16) float g_Wot[C * C];
static __device__ __align__(16) float g_Wdt[C * C];

__device__ __forceinline__ float ssp_f(float x) {
    float t = __expf(-fabsf(x));
    return fmaxf(x, 0.0f) + __logf(1.0f + t) - 0.693147180559945f;
}

__device__ __forceinline__ float to_tf32(float x) {
    uint32_t u;
    asm("cvt.rna.tf32.f32 %0, %1;" : "=r"(u) : "f"(x));
    return __uint_as_float(u);
}

__device__ __forceinline__ void mma_tf32(float* d, const uint32_t* a, const uint32_t* b) {
    asm volatile(
        "mma.sync.aligned.m16n8k8.row.col.f32.tf32.tf32.f32 "
        "{%0,%1,%2,%3}, {%4,%5,%6,%7}, {%8,%9}, {%0,%1,%2,%3};"
        : "+f"(d[0]), "+f"(d[1]), "+f"(d[2]), "+f"(d[3])
        : "r"(a[0]), "r"(a[1]), "r"(a[2]), "r"(a[3]), "r"(b[0]), "r"(b[1]));
}

// Octet k-interleave: logical k j8 -> phys ((j8&3)<<1)|(j8>>2); pair {2c,2c+1} is one LDS.64.

__device__ __forceinline__ void load_w_tile(float* dst, const float* __restrict__ src,
                                            int tid, int nthr) {
    for (int idx = tid; idx < 128 * 32; idx += nthr) {
        int row = idx >> 5, c4 = idx & 31;
        float4 v = ((const float4*)src)[idx];
        float* d = dst + row * LDK + (c4 >> 1) * 8 + (c4 & 1);
        d[0] = to_tf32(v.x); d[2] = to_tf32(v.y); d[4] = to_tf32(v.z); d[6] = to_tf32(v.w);
    }
}

__device__ __forceinline__ void load_a_tile(float* dst, const float* __restrict__ src,
                                            int base, int nrow_total, int rows,
                                            int tid, int nthr) {
    for (int idx = tid; idx < rows * 32; idx += nthr) {
        int row = idx >> 5, c4 = idx & 31;
        float4 v = make_float4(0.f, 0.f, 0.f, 0.f);
        int gr = base + row;
        if (gr < nrow_total) v = ((const float4*)src)[gr * 32 + c4];
        float* d = dst + row * LDK + (c4 >> 1) * 8 + (c4 & 1);
        d[0] = to_tf32(v.x); d[2] = to_tf32(v.y); d[4] = to_tf32(v.z); d[6] = to_tf32(v.w);
    }
}

// one warp's 32x32 output tile over k=128
__device__ __forceinline__ void gemm32x32(const float* pa, const float* pb, float acc[2][4][4]) {
#pragma unroll
    for (int mt = 0; mt < 2; ++mt)
#pragma unroll
        for (int nt = 0; nt < 4; ++nt)
#pragma unroll
            for (int q = 0; q < 4; ++q) acc[mt][nt][q] = 0.f;
#pragma unroll
    for (int kk = 0; kk < 16; ++kk) {
        const int kb = kk * 8;
        uint32_t af[2][4], bf[4][2];
#pragma unroll
        for (int mt = 0; mt < 2; ++mt) {
            float2 xv = *(const float2*)(pa + mt * 16 * LDK + kb);
            float2 yv = *(const float2*)(pa + (mt * 16 + 8) * LDK + kb);
            af[mt][0] = __float_as_uint(xv.x); af[mt][2] = __float_as_uint(xv.y);
            af[mt][1] = __float_as_uint(yv.x); af[mt][3] = __float_as_uint(yv.y);
        }
#pragma unroll
        for (int nt = 0; nt < 4; ++nt) {
            float2 zv = *(const float2*)(pb + nt * 8 * LDK + kb);
            bf[nt][0] = __float_as_uint(zv.x); bf[nt][1] = __float_as_uint(zv.y);
        }
#pragma unroll
        for (int mt = 0; mt < 2; ++mt)
#pragma unroll
            for (int nt = 0; nt < 4; ++nt)
                mma_tf32(acc[mt][nt], af[mt], bf[nt]);
    }
}

#define BARG() asm volatile("bar.sync %0, 128;" :: "r"(grp + 1) : "memory")

// =====================================================================
// Edge kernel: 4 independent 4-warp groups; register-prefetched A tiles.
// agg += scatter( ssp(ssp(dijk@W1+b1)@W2+b2) * xf[idx_j] )
// =====================================================================
extern "C" __global__ void __launch_bounds__(512, 1)
k_edges_mma(const float* __restrict__ dijk,
            const int* __restrict__ idx_j,
            const int* __restrict__ seg_i,
            const int* __restrict__ seg_j,
            const float* __restrict__ b1, const float* __restrict__ b2,
            int ne, int ntt) {
    float* sA0 = (float*)dynsmem;                 // NG x (32 x LDK)
    float* sB1 = sA0 + NG * TME * LDK;            // W1t 128 x LDK
    float* sB2 = sB1 + 128 * LDK;                 // W2t 128 x LDK
    int*   sg  = (int*)(sB2 + 128 * LDK);         // [NG][64] gather
    float* sb1 = (float*)(sg + NG * 64);          // bias1 [128]
    float* sb2 = sb1 + 128;                       // bias2 [128]

    const int tid = threadIdx.x;
    const int grp = tid >> 7, gt = tid & 127;     // 4 groups of 128 threads
    const int wid = gt >> 5, lane = tid & 31;
    const int g = lane >> 2, c = lane & 3;
    const int nc = wid * 32;                      // warp col-block (mr = 0 for all)
    const int pe = ((c & 1) << 2) + (c >> 1);     // phys pos of logical col 2c within octet
    const int po = pe + 2;

    float* sA  = sA0 + grp * TME * LDK;
    int* s_aj = sg + grp * 64;
    int* s_ti = s_aj + TME;

    if (tid < 128) sb1[tid] = b1[tid];
    else if (tid < 256) sb2[tid - 128] = b2[tid - 128];

    load_w_tile(sB1, g_W1t, tid, 512);
    load_w_tile(sB2, g_W2t, tid, 512);
    __syncthreads();

    const float* pa  = sA  + g * LDK + 2 * c;
    const float* pb1 = sB1 + (nc + g) * LDK + 2 * c;
    const float* pb2 = sB2 + (nc + g) * LDK + 2 * c;

    const int tstride = gridDim.x * NG;
    int t = blockIdx.x * NG + grp;

    // per-thread A-row mapping for the 8 prefetch quads
    const int prow = gt >> 5;        // base row (advances by 4 per quad)
    const int pc4  = gt & 31;

    // ---- prologue prefetch for first tile ----
    float4 pf[8];
    int pf_aj = 0, pf_ti = -1;
    {
        int base = t * TME;
#pragma unroll
        for (int i = 0; i < 8; ++i) {
            int gr = base + prow + i * 4;
            pf[i] = (t < ntt && gr < ne) ? ((const float4*)dijk)[gr * 32 + pc4]
                                         : make_float4(0.f, 0.f, 0.f, 0.f);
        }
        if (gt < TME) {
            int e = base + gt;
            if (t < ntt && e < ne) { int p = seg_j[e]; pf_aj = idx_j[p]; pf_ti = seg_i[p]; }
        }
    }

    for (; t < ntt; ) {
        // ---- commit prefetched tile to smem ----
#pragma unroll
        for (int i = 0; i < 8; ++i) {
            int row = prow + i * 4;
            float* d = sA + row * LDK + (pc4 >> 1) * 8 + (pc4 & 1);
            d[0] = to_tf32(pf[i].x); d[2] = to_tf32(pf[i].y);
            d[4] = to_tf32(pf[i].z); d[6] = to_tf32(pf[i].w);
        }
        if (gt < TME) { s_aj[gt] = pf_aj; s_ti[gt] = pf_ti; }
        BARG();

        // ---- issue prefetch for next tile (drains behind the GEMMs) ----
        const int tn = t + tstride;
        {
            int base = tn * TME;
#pragma unroll
            for (int i = 0; i < 8; ++i) {
                int gr = base + prow + i * 4;
                pf[i] = (tn < ntt && gr < ne) ? ((const float4*)dijk)[gr * 32 + pc4]
                                              : make_float4(0.f, 0.f, 0.f, 0.f);
            }
            pf_aj = 0; pf_ti = -1;
            if (gt < TME) {
                int e = base + gt;
                if (tn < ntt && e < ne) { int p = seg_j[e]; pf_aj = idx_j[p]; pf_ti = seg_i[p]; }
            }
        }

        float acc[2][4][4];
        gemm32x32(pa, pb1, acc);
        BARG();

        // epi1: H = tf32(ssp(D + b1)) -> sA
#pragma unroll
        for (int mt = 0; mt < 2; ++mt) {
            int row = mt * 16 + g;
#pragma unroll
            for (int nt = 0; nt < 4; ++nt) {
                int col = nc + nt * 8 + 2 * c;
                float2 bb = *(const float2*)(sb1 + col);
                float* d0 = sA + row * LDK + nc + nt * 8;
                float* d1 = d0 + 8 * LDK;
                d0[pe] = to_tf32(ssp_f(acc[mt][nt][0] + bb.x));
                d0[po] = to_tf32(ssp_f(acc[mt][nt][1] + bb.y));
                d1[pe] = to_tf32(ssp_f(acc[mt][nt][2] + bb.x));
                d1[po] = to_tf32(ssp_f(acc[mt][nt][3] + bb.y));
            }
        }
        BARG();

        gemm32x32(pa, pb2, acc);
        BARG();

        // epi2a: W = ssp(D + b2) -> sA (fp32)
#pragma unroll
        for (int mt = 0; mt < 2; ++mt) {
            int row = mt * 16 + g;
#pragma unroll
            for (int nt = 0; nt < 4; ++nt) {
                int col = nc + nt * 8 + 2 * c;
                float2 bb = *(const float2*)(sb2 + col);
                float* d0 = sA + row * LDK + nc + nt * 8;
                float* d1 = d0 + 8 * LDK;
                d0[pe] = ssp_f(acc[mt][nt][0] + bb.x);
                d0[po] = ssp_f(acc[mt][nt][1] + bb.y);
                d1[pe] = ssp_f(acc[mt][nt][2] + bb.x);
                d1[po] = ssp_f(acc[mt][nt][3] + bb.y);
            }
        }
        BARG();

        // epi2b: msg = W * xf[aj]; run-length reduce over sorted targets
        {
            const int col = gt;
            const int pc = (col & ~7) + ((col & 3) << 1) + ((col >> 2) & 1);
            float acc1 = 0.f;
            int cur = -1;
#pragma unroll
            for (int row = 0; row < TME; ++row) {
                int tgt = s_ti[row];
                float wv = sA[row * LDK + pc];
                float xv = __ldg(&g_xf[(size_t)s_aj[row] * C + col]);
                if (tgt != cur) {
                    if (cur >= 0) atomicAdd(&g_agg[(size_t)cur * C + col], acc1);
                    acc1 = 0.f; cur = tgt;
                }
                acc1 = fmaf(wv, xv, acc1);
            }
            if (cur >= 0) atomicAdd(&g_agg[(size_t)cur * C + col], acc1);
        }
        BARG();
        t = tn;
    }
}

// =====================================================================
// k_xf: xf = x @ Wi (tf32 mma), also zeroes g_agg rows of this tile
// =====================================================================
extern "C" __global__ void __launch_bounds__(512, 1)
k_xf_mma(const float* __restrict__ x, int na) {
    float* sA = (float*)dynsmem;        // 128 x LDK
    float* sB = sA + 128 * LDK;         // Wit
    const int tid = threadIdx.x, wid = tid >> 5, lane = tid & 31;
    const int g = lane >> 2, c = lane & 3;
    const int mr = (wid & 3) * 32, nc = (wid >> 2) * 32;
    const int base = blockIdx.x * 128;

    for (int idx = tid; idx < 128 * 32; idx += 512) {
        int row = idx >> 5, c4 = idx & 31;
        int gr = base + row;
        if (gr < na) ((float4*)(g_agg + (size_t)gr * C))[c4] = make_float4(0.f, 0.f, 0.f, 0.f);
    }
    load_w_tile(sB, g_Wit, tid, 512);
    load_a_tile(sA, x, base, na, 128, tid, 512);
    __syncthreads();

    float acc[2][4][4];
    gemm32x32(sA + (mr + g) * LDK + 2 * c, sB + (nc + g) * LDK + 2 * c, acc);

#pragma unroll
    for (int mt = 0; mt < 2; ++mt)
#pragma unroll
        for (int half = 0; half < 2; ++half) {
            int r = base + mr + mt * 16 + half * 8 + g;
            if (r < na) {
#pragma unroll
                for (int nt = 0; nt < 4; ++nt) {
                    int col = nc + nt * 8 + 2 * c;
                    float2 v = make_float2(acc[mt][nt][half * 2], acc[mt][nt][half * 2 + 1]);
                    *(float2*)(&g_xf[(size_t)r * C + col]) = v;
                }
            }
        }
}

// =====================================================================
// k_out: h = ssp(agg@Wo+bo); v = h@Wd+bd; y = x+v; writes (y, v)
// =====================================================================
extern "C" __global__ void __launch_bounds__(512, 1)
k_out_mma(const float* __restrict__ x,
          const float* __restrict__ bo, const float* __restrict__ bd,
          float* __restrict__ out_y, float* __restrict__ out_v, int na) {
    float* sA  = (float*)dynsmem;       // 128 x LDK
    float* sBo = sA + 128 * LDK;        // Wot
    float* sBd = sBo + 128 * LDK;       // Wdt
    const int tid = threadIdx.x, wid = tid >> 5, lane = tid & 31;
    const int g = lane >> 2, c = lane & 3;
    const int mr = (wid & 3) * 32, nc = (wid >> 2) * 32;
    const int pe = ((c & 1) << 2) + (c >> 1);
    const int po = pe + 2;
    const int base = blockIdx.x * 128;

    float boe[4], boo[4], bde[4], bdo[4];
#pragma unroll
    for (int nt = 0; nt < 4; ++nt) {
        int col = nc + nt * 8 + 2 * c;
        boe[nt] = bo[col]; boo[nt] = bo[col + 1];
        bde[nt] = bd[col]; bdo[nt] = bd[col + 1];
    }

    load_w_tile(sBo, g_Wot, tid, 512);
    load_w_tile(sBd, g_Wdt, tid, 512);
    load_a_tile(sA, g_agg, base, na, 128, tid, 512);
    __syncthreads();

    const float* pa = sA + (mr + g) * LDK + 2 * c;
    float acc[2][4][4];
    gemm32x32(pa, sBo + (nc + g) * LDK + 2 * c, acc);
    __syncthreads();   // all warps done reading sA

    // epi1: H = tf32(ssp(D + bo)) -> sA
#pragma unroll
    for (int mt = 0; mt < 2; ++mt) {
        int row = mr + mt * 16 + g;
#pragma unroll
        for (int nt = 0; nt < 4; ++nt) {
            float* d0 = sA + row * LDK + nc + nt * 8;
            float* d1 = d0 + 8 * LDK;
            d0[pe] = to_tf32(ssp_f(acc[mt][nt][0] + boe[nt]));
            d0[po] = to_tf32(ssp_f(acc[mt][nt][1] + boo[nt]));
            d1[pe] = to_tf32(ssp_f(acc[mt][nt][2] + boe[nt]));
            d1[po] = to_tf32(ssp_f(acc[mt][nt][3] + boo[nt]));
        }
    }
    __syncthreads();

    gemm32x32(pa, sBd + (nc + g) * LDK + 2 * c, acc);

    // final epilogue: v = D + bd; y = x + v
#pragma unroll
    for (int mt = 0; mt < 2; ++mt)
#pragma unroll
        for (int half = 0; half < 2; ++half) {
            int r = base + mr + mt * 16 + half * 8 + g;
            if (r < na) {
#pragma unroll
                for (int nt = 0; nt < 4; ++nt) {
                    int col = nc + nt * 8 + 2 * c;
                    float vx = acc[mt][nt][half * 2]     + bde[nt];
                    float vy = acc[mt][nt][half * 2 + 1] + bdo[nt];
                    float2 xv = *(const float2*)(&x[(size_t)r * C + col]);
                    *(float2*)(&out_v[(size_t)r * C + col]) = make_float2(vx, vy);
                    *(float2*)(&out_y[(size_t)r * C + col]) = make_float2(xv.x + vx, xv.y + vy);
                }
            }
        }
}

// ---------------- transpose 5 weights W[k][n] -> Wt[n][k] ----------------
extern "C" __global__ void k_tr5(const float* __restrict__ s0, const float* __restrict__ s1,
                                 const float* __restrict__ s2, const float* __restrict__ s3,
                                 const float* __restrict__ s4) {
    __shared__ float t[32][33];
    const float* s; float* d;
    switch (blockIdx.z) {
        case 0: s = s0; d = g_W1t; break;
        case 1: s = s1; d = g_W2t; break;
        case 2: s = s2; d = g_Wit; break;
        case 3: s = s3; d = g_Wot; break;
        default: s = s4; d = g_Wdt; break;
    }
    int bx = blockIdx.x, by = blockIdx.y;
    int xx = threadIdx.x, yy = threadIdx.y;
#pragma unroll
    for (int i = 0; i < 32; i += 8) t[yy + i][xx] = s[(by * 32 + yy + i) * C + bx * 32 + xx];
    __syncthreads();
#pragma unroll
    for (int i = 0; i < 32; i += 8) d[(bx * 32 + yy + i) * C + by * 32 + xx] = t[xx][yy + i];
}

// ============================ launch ============================
extern "C" void kernel_launch(void* const* d_in, const int* in_sizes, int n_in,
                              void* d_out, int out_size) {
    const float* x    = (const float*)d_in[0];
    const float* dijk = (const float*)d_in[1];
    const int*   idxj = (const int*)d_in[2];
    const int*   segi = (const int*)d_in[3];
    const int*   segj = (const int*)d_in[4];
    const float* W1   = (const float*)d_in[5];
    const float* b1   = (const float*)d_in[6];
    const float* W2   = (const float*)d_in[7];
    const float* b2   = (const float*)d_in[8];
    const float* Wi   = (const float*)d_in[9];
    const float* Wo   = (const float*)d_in[10];
    const float* bo   = (const float*)d_in[11];
    const float* Wd   = (const float*)d_in[12];
    const float* bd   = (const float*)d_in[13];

    int na = in_sizes[0] / C;
    int ne = in_sizes[2];
    int ntt = (ne + TME - 1) / TME;
    int g_atoms = (na + 127) / 128;

    float* out_y = (float*)d_out;
    float* out_v = out_y + (size_t)na * C;

    const int SM_XF   = 2 * 128 * LDK * 4;                          // 139264
    const int SM_OUT  = 3 * 128 * LDK * 4;                          // 208896
    const int SM_EDGE = (NG * TME + 2 * 128) * LDK * 4 + 2048;      // 210944

    cudaFuncSetAttribute(k_xf_mma,    cudaFuncAttributeMaxDynamicSharedMemorySize, SM_XF);
    cudaFuncSetAttribute(k_out_mma,   cudaFuncAttributeMaxDynamicSharedMemorySize, SM_OUT);
    cudaFuncSetAttribute(k_edges_mma, cudaFuncAttributeMaxDynamicSharedMemorySize, SM_EDGE);

    k_tr5<<<dim3(4, 4, 5), dim3(32, 8)>>>(W1, W2, Wi, Wo, Wd);
    k_xf_mma<<<g_atoms, 512, SM_XF>>>(x, na);
    k_edges_mma<<<148, 512, SM_EDGE>>>(dijk, idxj, segi, segj, b1, b2, ne, ntt);
    k_out_mma<<<g_atoms, 512, SM_OUT>>>(x, bo, bd, out_y, out_v, na);
}